// round 1
// baseline (speedup 1.0000x reference)
#include <cuda_runtime.h>
#include <math.h>

#define NNODES 100000
#define NCELLS 200000
#define NEDGES 300000
#define DIM 128
#define TWOE (2*NEDGES)
#define THREEC (3*NCELLS)

// ---------------- scratch (static device globals: allocation-free) ----------
__device__ float g_att[TWOE];                       // exp(logit) per (edge,target) pair
__device__ float g_nodesum[NNODES];                 // softmax denominators
__device__ float g_counts[NNODES];                  // node incidence counts (as float)
__device__ float g_nodeagg[(size_t)NNODES * DIM];   // attention-weighted node aggregate

// ---------------- zero init ----------------
__global__ void zero_kernel(float* __restrict__ node_out) {
    int i = blockIdx.x * 256 + threadIdx.x;
    if (i < NNODES * DIM) { g_nodeagg[i] = 0.f; node_out[i] = 0.f; }
    if (i < NNODES)       { g_nodesum[i] = 0.f; g_counts[i] = 0.f; }
}

// ---------------- attention logits + exp + segment sum ----------------
// one warp per (edge,target) pair; 32 lanes x float4 covers DIM=128 exactly
__global__ void attn_kernel(const float* __restrict__ edge_attr,
                            const float* __restrict__ node_emb,
                            const int*   __restrict__ edge_index) {
    int w    = (blockIdx.x * blockDim.x + threadIdx.x) >> 5;
    int lane = threadIdx.x & 31;
    if (w >= TWOE) return;
    int e = (w < NEDGES) ? w : w - NEDGES;
    // two_out = concat(receivers, senders); edge_index row0=senders, row1=receivers
    int t = (w < NEDGES) ? edge_index[NEDGES + w] : edge_index[w - NEDGES];

    float4 a = __ldg(((const float4*)edge_attr) + e * 32 + lane);
    float4 b = __ldg(((const float4*)node_emb)  + t * 32 + lane);
    float d = a.x * b.x + a.y * b.y + a.z * b.z + a.w * b.w;
    #pragma unroll
    for (int off = 16; off > 0; off >>= 1)
        d += __shfl_xor_sync(0xffffffffu, d, off);

    if (lane == 0) {
        // 1/sqrt(128); softmax max-shift skipped (|logit| <= ~11, exp is safe)
        float v = expf(d * 0.08838834764831845f);
        g_att[w] = v;
        atomicAdd(&g_nodesum[t], v);
    }
}

// ---------------- weighted scatter of edge features into node_agg -----------
__global__ void scatter_edge_kernel(const float* __restrict__ edge_attr,
                                    const int*   __restrict__ edge_index) {
    int w    = (blockIdx.x * blockDim.x + threadIdx.x) >> 5;
    int lane = threadIdx.x & 31;
    if (w >= TWOE) return;
    int e = (w < NEDGES) ? w : w - NEDGES;
    int t = (w < NEDGES) ? edge_index[NEDGES + w] : edge_index[w - NEDGES];

    float wgt = g_att[w] / g_nodesum[t];
    float4 a = __ldg(((const float4*)edge_attr) + e * 32 + lane);
    float* dst = g_nodeagg + (size_t)t * DIM + lane * 4;
    asm volatile("red.global.add.v4.f32 [%0], {%1,%2,%3,%4};"
                 :: "l"(dst), "f"(a.x * wgt), "f"(a.y * wgt),
                    "f"(a.z * wgt), "f"(a.w * wgt)
                 : "memory");
}

// ---------------- fused MLP: gather(face)->concat->GEMM1->relu->GEMM2 -------
// block = 128 cells x 128 outputs, 256 threads, 8x8 microtiles, BK=16
#define MLP_SMEM_BYTES ((16*128 + 16*128 + 128*132) * 4 + 3*128*4)

__global__ __launch_bounds__(256, 2)
void mlp_kernel(const float* __restrict__ cell_attr,
                const int*   __restrict__ face,
                const float* __restrict__ W1, const float* __restrict__ b1,
                const float* __restrict__ W2, const float* __restrict__ b2,
                float* __restrict__ out) {
    extern __shared__ float smem[];
    float* sA = smem;                 // [16][128] A tile (k-major)
    float* sB = sA + 16 * 128;        // [16][128] weight tile
    float* sH = sB + 16 * 128;        // [128][132] hidden activations (padded)
    int*   sF = (int*)(sH + 128 * 132); // [3][128] face ids for this block

    const int tid = threadIdx.x;
    const int tx = tid & 15, ty = tid >> 4;
    const int cx = tx * 8, ry = ty * 8;
    const int rowBase = blockIdx.x * 128;

    if (tid < 128) {
        int r = rowBase + tid;
        if (r < NCELLS) {
            sF[tid]       = face[r];
            sF[128 + tid] = face[NCELLS + r];
            sF[256 + tid] = face[2 * NCELLS + r];
        } else {
            sF[tid] = 0; sF[128 + tid] = 0; sF[256 + tid] = 0;
        }
    }
    __syncthreads();

    float acc[8][8];
    #pragma unroll
    for (int i = 0; i < 8; i++)
        #pragma unroll
        for (int j = 0; j < 8; j++) acc[i][j] = 0.f;

    const float inv3 = 1.f / 3.f;

    // -------- GEMM1: [128 x 256] @ W1[256 x 128], A = concat(cell_attr, cell_agg)
    for (int kb = 0; kb < 16; kb++) {
        #pragma unroll
        for (int j = 0; j < 2; j++) {
            int li = tid + j * 256;          // 0..511
            int m  = li >> 2, kq = li & 3;
            int kg = kb * 16 + kq * 4;
            int r  = rowBase + m;
            float4 v = make_float4(0.f, 0.f, 0.f, 0.f);
            if (r < NCELLS) {
                if (kg < 128) {
                    v = *(const float4*)(cell_attr + (size_t)r * 128 + kg);
                } else {
                    int k2 = kg - 128;
                    float4 v0 = *(const float4*)(g_nodeagg + (size_t)sF[m]       * 128 + k2);
                    float4 v1 = *(const float4*)(g_nodeagg + (size_t)sF[128 + m] * 128 + k2);
                    float4 v2 = *(const float4*)(g_nodeagg + (size_t)sF[256 + m] * 128 + k2);
                    v.x = (v0.x + v1.x + v2.x) * inv3;
                    v.y = (v0.y + v1.y + v2.y) * inv3;
                    v.z = (v0.z + v1.z + v2.z) * inv3;
                    v.w = (v0.w + v1.w + v2.w) * inv3;
                }
            }
            sA[(kq * 4 + 0) * 128 + m] = v.x;
            sA[(kq * 4 + 1) * 128 + m] = v.y;
            sA[(kq * 4 + 2) * 128 + m] = v.z;
            sA[(kq * 4 + 3) * 128 + m] = v.w;
        }
        #pragma unroll
        for (int j = 0; j < 2; j++) {
            int li = tid + j * 256;
            int kq = li >> 5, n4 = (li & 31) * 4;
            *(float4*)(sB + kq * 128 + n4) =
                *(const float4*)(W1 + (size_t)(kb * 16 + kq) * 128 + n4);
        }
        __syncthreads();
        #pragma unroll
        for (int kk = 0; kk < 16; kk++) {
            float4 a0 = *(float4*)(sA + kk * 128 + ry);
            float4 a1 = *(float4*)(sA + kk * 128 + ry + 4);
            float4 b0 = *(float4*)(sB + kk * 128 + cx);
            float4 b1v = *(float4*)(sB + kk * 128 + cx + 4);
            float av[8] = {a0.x, a0.y, a0.z, a0.w, a1.x, a1.y, a1.z, a1.w};
            float bv[8] = {b0.x, b0.y, b0.z, b0.w, b1v.x, b1v.y, b1v.z, b1v.w};
            #pragma unroll
            for (int i = 0; i < 8; i++)
                #pragma unroll
                for (int j = 0; j < 8; j++)
                    acc[i][j] = fmaf(av[i], bv[j], acc[i][j]);
        }
        __syncthreads();
    }

    // -------- h = relu(acc + b1) -> sH ; reset acc
    {
        float bb[8];
        #pragma unroll
        for (int j = 0; j < 8; j++) bb[j] = __ldg(b1 + cx + j);
        #pragma unroll
        for (int i = 0; i < 8; i++) {
            float4 h0, h1;
            h0.x = fmaxf(acc[i][0] + bb[0], 0.f);
            h0.y = fmaxf(acc[i][1] + bb[1], 0.f);
            h0.z = fmaxf(acc[i][2] + bb[2], 0.f);
            h0.w = fmaxf(acc[i][3] + bb[3], 0.f);
            h1.x = fmaxf(acc[i][4] + bb[4], 0.f);
            h1.y = fmaxf(acc[i][5] + bb[5], 0.f);
            h1.z = fmaxf(acc[i][6] + bb[6], 0.f);
            h1.w = fmaxf(acc[i][7] + bb[7], 0.f);
            *(float4*)(sH + (ry + i) * 132 + cx)     = h0;
            *(float4*)(sH + (ry + i) * 132 + cx + 4) = h1;
        }
        #pragma unroll
        for (int i = 0; i < 8; i++)
            #pragma unroll
            for (int j = 0; j < 8; j++) acc[i][j] = 0.f;
    }

    // -------- GEMM2: h[128 x 128] @ W2[128 x 128]
    for (int kb = 0; kb < 8; kb++) {
        __syncthreads();   // sH visible (first iter) / prior compute done with sB
        #pragma unroll
        for (int j = 0; j < 2; j++) {
            int li = tid + j * 256;
            int kq = li >> 5, n4 = (li & 31) * 4;
            *(float4*)(sB + kq * 128 + n4) =
                *(const float4*)(W2 + (size_t)(kb * 16 + kq) * 128 + n4);
        }
        __syncthreads();
        #pragma unroll
        for (int kk = 0; kk < 16; kk++) {
            int k = kb * 16 + kk;
            float av[8];
            #pragma unroll
            for (int i = 0; i < 8; i++) av[i] = sH[(ry + i) * 132 + k];
            float4 b0 = *(float4*)(sB + kk * 128 + cx);
            float4 b1v = *(float4*)(sB + kk * 128 + cx + 4);
            float bv[8] = {b0.x, b0.y, b0.z, b0.w, b1v.x, b1v.y, b1v.z, b1v.w};
            #pragma unroll
            for (int i = 0; i < 8; i++)
                #pragma unroll
                for (int j = 0; j < 8; j++)
                    acc[i][j] = fmaf(av[i], bv[j], acc[i][j]);
        }
    }

    // -------- epilogue: out = acc + b2
    {
        float bb[8];
        #pragma unroll
        for (int j = 0; j < 8; j++) bb[j] = __ldg(b2 + cx + j);
        #pragma unroll
        for (int i = 0; i < 8; i++) {
            int r = rowBase + ry + i;
            if (r < NCELLS) {
                float4 o0, o1;
                o0.x = acc[i][0] + bb[0]; o0.y = acc[i][1] + bb[1];
                o0.z = acc[i][2] + bb[2]; o0.w = acc[i][3] + bb[3];
                o1.x = acc[i][4] + bb[4]; o1.y = acc[i][5] + bb[5];
                o1.z = acc[i][6] + bb[6]; o1.w = acc[i][7] + bb[7];
                *(float4*)(out + (size_t)r * 128 + cx)     = o0;
                *(float4*)(out + (size_t)r * 128 + cx + 4) = o1;
            }
        }
    }
}

// ---------------- scatter cell outputs to node sums + counts ----------------
__global__ void scatter_cell_kernel(const float* __restrict__ cell_out,
                                    const int*   __restrict__ face,
                                    float* __restrict__ node_out) {
    int w    = (blockIdx.x * blockDim.x + threadIdx.x) >> 5;
    int lane = threadIdx.x & 31;
    if (w >= THREEC) return;
    int node = face[w];                 // flat concat(face[0],face[1],face[2])
    int c = w;
    if (c >= NCELLS) c -= NCELLS;
    if (c >= NCELLS) c -= NCELLS;

    float4 v = __ldg(((const float4*)cell_out) + c * 32 + lane);
    float* dst = node_out + (size_t)node * DIM + lane * 4;
    asm volatile("red.global.add.v4.f32 [%0], {%1,%2,%3,%4};"
                 :: "l"(dst), "f"(v.x), "f"(v.y), "f"(v.z), "f"(v.w)
                 : "memory");
    if (lane == 0) atomicAdd(&g_counts[node], 1.f);
}

// ---------------- divide node sums by counts ----------------
__global__ void finalize_kernel(float* __restrict__ node_out) {
    int i = blockIdx.x * 256 + threadIdx.x;
    if (i >= NNODES * DIM / 4) return;
    float inv = 1.f / fmaxf(g_counts[i >> 5], 1.f);
    float4 v = ((float4*)node_out)[i];
    v.x *= inv; v.y *= inv; v.z *= inv; v.w *= inv;
    ((float4*)node_out)[i] = v;
}

// ---------------- launch ----------------
extern "C" void kernel_launch(void* const* d_in, const int* in_sizes, int n_in,
                              void* d_out, int out_size) {
    const float* cell_attr  = (const float*)d_in[0];
    const float* edge_attr  = (const float*)d_in[1];
    const float* node_emb   = (const float*)d_in[2];
    const int*   edge_index = (const int*)d_in[3];
    const int*   face       = (const int*)d_in[4];
    const float* W1 = (const float*)d_in[5];
    const float* b1 = (const float*)d_in[6];
    const float* W2 = (const float*)d_in[7];
    const float* b2 = (const float*)d_in[8];

    float* out      = (float*)d_out;
    float* cell_out = out;                         // [NCELLS, 128]
    float* node_out = out + (size_t)NCELLS * DIM;  // [NNODES, 128]

    cudaFuncSetAttribute(mlp_kernel,
                         cudaFuncAttributeMaxDynamicSharedMemorySize,
                         MLP_SMEM_BYTES);

    zero_kernel<<<50000, 256>>>(node_out);
    attn_kernel<<<75000, 256>>>(edge_attr, node_emb, edge_index);
    scatter_edge_kernel<<<75000, 256>>>(edge_attr, edge_index);
    mlp_kernel<<<1563, 256, MLP_SMEM_BYTES>>>(cell_attr, face, W1, b1, W2, b2, cell_out);
    scatter_cell_kernel<<<75000, 256>>>(cell_out, face, node_out);
    finalize_kernel<<<12500, 256>>>(node_out);
}

// round 3
// speedup vs baseline: 1.6016x; 1.6016x over previous
#include <cuda_runtime.h>
#include <math.h>
#include <cstdint>

#define NNODES 100000
#define NCELLS 200000
#define NEDGES 300000
#define DIM 128
#define THREEC (3*NCELLS)

// ---------------- scratch (static device globals: allocation-free) ----------
__device__ float g_nodesum[NNODES];
__device__ float g_counts[NNODES];
__device__ float g_nodeagg[(size_t)NNODES * DIM];

// ---------------- helpers ----------------
__device__ __forceinline__ uint32_t rna(float x) {
    uint32_t u; asm("cvt.rna.tf32.f32 %0, %1;" : "=r"(u) : "f"(x)); return u;
}
__device__ __forceinline__ float rnaf(float x) { return __uint_as_float(rna(x)); }

__device__ __forceinline__ void mma8(float c[4], const uint32_t a[4], const uint32_t b[2]) {
    asm volatile("mma.sync.aligned.m16n8k8.row.col.f32.tf32.tf32.f32 "
        "{%0,%1,%2,%3}, {%4,%5,%6,%7}, {%8,%9}, {%0,%1,%2,%3};"
        : "+f"(c[0]), "+f"(c[1]), "+f"(c[2]), "+f"(c[3])
        : "r"(a[0]), "r"(a[1]), "r"(a[2]), "r"(a[3]), "r"(b[0]), "r"(b[1]));
}

// ---------------- zero init ----------------
__global__ void zero_kernel(float* __restrict__ node_out) {
    int i = blockIdx.x * 256 + threadIdx.x;
    if (i < NNODES * DIM) { g_nodeagg[i] = 0.f; node_out[i] = 0.f; }
    if (i < NNODES)       { g_nodesum[i] = 0.f; g_counts[i] = 0.f; }
}

// ---------------- fused attention: one warp per EDGE, both directions -------
// two_out = concat(receivers, senders): dot(edge, emb[r]) -> scatter to r,
//                                       dot(edge, emb[s]) -> scatter to s.
// Scatter UNNORMALIZED e*x and accumulate denominators; normalize afterwards.
__global__ void attn_kernel(const float* __restrict__ edge_attr,
                            const float* __restrict__ node_emb,
                            const int*   __restrict__ edge_index) {
    int e    = (blockIdx.x * blockDim.x + threadIdx.x) >> 5;
    int lane = threadIdx.x & 31;
    if (e >= NEDGES) return;
    int s = __ldg(edge_index + e);
    int r = __ldg(edge_index + NEDGES + e);

    float4 a  = __ldg(((const float4*)edge_attr) + (size_t)e * 32 + lane);
    float4 bs = __ldg(((const float4*)node_emb)  + (size_t)s * 32 + lane);
    float4 br = __ldg(((const float4*)node_emb)  + (size_t)r * 32 + lane);
    float ds = a.x * bs.x + a.y * bs.y + a.z * bs.z + a.w * bs.w;
    float dr = a.x * br.x + a.y * br.y + a.z * br.z + a.w * br.w;
    #pragma unroll
    for (int off = 16; off > 0; off >>= 1) {
        ds += __shfl_xor_sync(0xffffffffu, ds, off);
        dr += __shfl_xor_sync(0xffffffffu, dr, off);
    }
    // 1/sqrt(128); logits bounded (~|11|) so no max-shift needed
    float es = expf(ds * 0.08838834764831845f);
    float er = expf(dr * 0.08838834764831845f);

    float* dstr = g_nodeagg + (size_t)r * DIM + lane * 4;
    asm volatile("red.global.add.v4.f32 [%0], {%1,%2,%3,%4};"
                 :: "l"(dstr), "f"(a.x * er), "f"(a.y * er), "f"(a.z * er), "f"(a.w * er)
                 : "memory");
    float* dsts = g_nodeagg + (size_t)s * DIM + lane * 4;
    asm volatile("red.global.add.v4.f32 [%0], {%1,%2,%3,%4};"
                 :: "l"(dsts), "f"(a.x * es), "f"(a.y * es), "f"(a.z * es), "f"(a.w * es)
                 : "memory");
    if (lane == 0) atomicAdd(&g_nodesum[r], er);
    if (lane == 1) atomicAdd(&g_nodesum[s], es);
}

// node_agg /= nodesum (guard empty segments)
__global__ void normalize_kernel() {
    int i = blockIdx.x * 256 + threadIdx.x;          // float4 index
    if (i >= NNODES * 32) return;
    float sum = g_nodesum[i >> 5];
    float inv = (sum > 0.f) ? (1.f / sum) : 0.f;
    float4 v = ((float4*)g_nodeagg)[i];
    v.x *= inv; v.y *= inv; v.z *= inv; v.w *= inv;
    ((float4*)g_nodeagg)[i] = v;
}

// ============================================================================
// fused MLP on tf32 mma.sync: gather(face)->concat->GEMM1->relu->GEMM2
// CTA = 128 cells x 128 outs, 256 threads (8 warps, warp tile 32x64)
// SMEM tiles k-major with row pad LDP=136 floats -> conflict-free frag loads
// ============================================================================
#define LDP 136
#define SA_OFF 0
#define SB_OFF (16*LDP)
#define SH_OFF (32*LDP)
#define B1_OFF (SH_OFF + 128*LDP)
#define B2_OFF (B1_OFF + 128)
#define SF_OFF (B2_OFF + 128)
#define SMEM_FLOATS (SF_OFF + 384)
#define MLP_SMEM (SMEM_FLOATS * 4)

__global__ __launch_bounds__(256, 1)
void mlp_mma_kernel(const float* __restrict__ cell_attr, const int* __restrict__ face,
                    const float* __restrict__ W1, const float* __restrict__ b1,
                    const float* __restrict__ W2, const float* __restrict__ b2,
                    float* __restrict__ out) {
    extern __shared__ float sm[];
    float* sA  = sm + SA_OFF;
    float* sB  = sm + SB_OFF;
    float* sH  = sm + SH_OFF;
    float* b1s = sm + B1_OFF;
    float* b2s = sm + B2_OFF;
    int*   sF  = (int*)(sm + SF_OFF);

    const int tid  = threadIdx.x;
    const int wid  = tid >> 5, lane = tid & 31;
    const int g    = lane >> 2, tig = lane & 3;
    const int m0   = (wid & 3) * 32, n0 = (wid >> 2) * 64;
    const int rowBase = blockIdx.x * 128;

    if (tid < 128) {
        b1s[tid] = b1[tid]; b2s[tid] = b2[tid];
        int r = rowBase + tid;
        bool ok = r < NCELLS;
        sF[tid]       = ok ? face[r] : 0;
        sF[128 + tid] = ok ? face[NCELLS + r] : 0;
        sF[256 + tid] = ok ? face[2 * NCELLS + r] : 0;
    }
    // sF/b1s first consumed after at least one __syncthreads below.

    float acc[2][8][4];
    #pragma unroll
    for (int mt = 0; mt < 2; mt++)
        #pragma unroll
        for (int nt = 0; nt < 8; nt++)
            #pragma unroll
            for (int q = 0; q < 4; q++) acc[mt][nt][q] = 0.f;

    float4 pa[2], pb[2];
    const float inv3 = 1.f / 3.f;

    // ---- prefetch helpers (c = 16-wide k chunk index) ----
    auto fetchA = [&](int c) {
        #pragma unroll
        for (int h = 0; h < 2; h++) {
            int j = tid + h * 256;               // float4 id within [16k x 128m]
            int m = j >> 2, k4 = (j & 3) * 4;
            float4 v = make_float4(0.f, 0.f, 0.f, 0.f);
            int r = rowBase + m;
            if (r < NCELLS) {
                if (c < 8) {
                    v = __ldg((const float4*)(cell_attr + (size_t)r * 128 + c * 16 + k4));
                } else {
                    int gk = (c - 8) * 16 + k4;
                    float4 a0 = __ldg((const float4*)(g_nodeagg + (size_t)sF[m]       * 128 + gk));
                    float4 a1 = __ldg((const float4*)(g_nodeagg + (size_t)sF[128 + m] * 128 + gk));
                    float4 a2 = __ldg((const float4*)(g_nodeagg + (size_t)sF[256 + m] * 128 + gk));
                    v.x = (a0.x + a1.x + a2.x) * inv3;
                    v.y = (a0.y + a1.y + a2.y) * inv3;
                    v.z = (a0.z + a1.z + a2.z) * inv3;
                    v.w = (a0.w + a1.w + a2.w) * inv3;
                }
            }
            pa[h] = v;
        }
    };
    auto storeA = [&]() {
        #pragma unroll
        for (int h = 0; h < 2; h++) {
            int j = tid + h * 256;
            int m = j >> 2, k4 = (j & 3) * 4;
            sA[(k4 + 0) * LDP + m] = rnaf(pa[h].x);
            sA[(k4 + 1) * LDP + m] = rnaf(pa[h].y);
            sA[(k4 + 2) * LDP + m] = rnaf(pa[h].z);
            sA[(k4 + 3) * LDP + m] = rnaf(pa[h].w);
        }
    };
    auto fetchB = [&](const float* W, int c) {
        #pragma unroll
        for (int h = 0; h < 2; h++) {
            int j = tid + h * 256;               // [16k x 128n]
            int k = j >> 5, n4 = (j & 31) * 4;
            pb[h] = __ldg((const float4*)(W + (size_t)(c * 16 + k) * 128 + n4));
        }
    };
    auto storeB = [&]() {
        #pragma unroll
        for (int h = 0; h < 2; h++) {
            int j = tid + h * 256;
            int k = j >> 5, n4 = (j & 31) * 4;
            float4 v;
            v.x = rnaf(pb[h].x); v.y = rnaf(pb[h].y);
            v.z = rnaf(pb[h].z); v.w = rnaf(pb[h].w);
            *(float4*)(sB + k * LDP + n4) = v;
        }
    };
    auto mmastep = [&](const float* Abase, int k0) {
        const float* ar = Abase + k0 * LDP;
        const float* br = sB + k0 * LDP;
        uint32_t af[2][4], bf[8][2];
        #pragma unroll
        for (int mt = 0; mt < 2; mt++) {
            int mm = m0 + 16 * mt + g;
            af[mt][0] = __float_as_uint(ar[tig * LDP + mm]);
            af[mt][1] = __float_as_uint(ar[tig * LDP + mm + 8]);
            af[mt][2] = __float_as_uint(ar[(tig + 4) * LDP + mm]);
            af[mt][3] = __float_as_uint(ar[(tig + 4) * LDP + mm + 8]);
        }
        #pragma unroll
        for (int nt = 0; nt < 8; nt++) {
            int nn = n0 + 8 * nt + g;
            bf[nt][0] = __float_as_uint(br[tig * LDP + nn]);
            bf[nt][1] = __float_as_uint(br[(tig + 4) * LDP + nn]);
        }
        #pragma unroll
        for (int mt = 0; mt < 2; mt++)
            #pragma unroll
            for (int nt = 0; nt < 8; nt++)
                mma8(acc[mt][nt], af[mt], bf[nt]);
    };

    // -------- GEMM1: concat(cell_attr, cell_agg)[128x256] @ W1 --------
    fetchA(0); fetchB(W1, 0);
    for (int c = 0; c < 16; c++) {
        storeA(); storeB();
        __syncthreads();
        if (c < 15) { fetchA(c + 1); fetchB(W1, c + 1); }
        mmastep(sA, 0);
        mmastep(sA, 8);
        __syncthreads();
    }

    // -------- epilogue 1: h = relu(D1 + b1) -> sH (k-major, tf32-rounded) ------
    #pragma unroll
    for (int mt = 0; mt < 2; mt++) {
        int row = m0 + 16 * mt + g;
        #pragma unroll
        for (int nt = 0; nt < 8; nt++) {
            int col = n0 + 8 * nt + 2 * tig;
            float bb0 = b1s[col], bb1 = b1s[col + 1];
            sH[col * LDP + row]           = rnaf(fmaxf(acc[mt][nt][0] + bb0, 0.f));
            sH[(col + 1) * LDP + row]     = rnaf(fmaxf(acc[mt][nt][1] + bb1, 0.f));
            sH[col * LDP + row + 8]       = rnaf(fmaxf(acc[mt][nt][2] + bb0, 0.f));
            sH[(col + 1) * LDP + row + 8] = rnaf(fmaxf(acc[mt][nt][3] + bb1, 0.f));
            acc[mt][nt][0] = 0.f; acc[mt][nt][1] = 0.f;
            acc[mt][nt][2] = 0.f; acc[mt][nt][3] = 0.f;
        }
    }
    __syncthreads();

    // -------- GEMM2: h[128x128] @ W2 --------
    fetchB(W2, 0);
    for (int c = 0; c < 8; c++) {
        storeB();
        __syncthreads();
        if (c < 7) fetchB(W2, c + 1);
        mmastep(sH + c * 16 * LDP, 0);
        mmastep(sH + c * 16 * LDP, 8);
        __syncthreads();
    }

    // -------- epilogue 2: out = D2 + b2 --------
    #pragma unroll
    for (int mt = 0; mt < 2; mt++) {
        int row = m0 + 16 * mt + g;
        if (rowBase + row < NCELLS) {
            float* o = out + (size_t)(rowBase + row) * 128;
            #pragma unroll
            for (int nt = 0; nt < 8; nt++) {
                int col = n0 + 8 * nt + 2 * tig;
                float2 v = make_float2(acc[mt][nt][0] + b2s[col],
                                       acc[mt][nt][1] + b2s[col + 1]);
                *(float2*)(o + col) = v;
            }
        }
        if (rowBase + row + 8 < NCELLS) {
            float* o = out + (size_t)(rowBase + row + 8) * 128;
            #pragma unroll
            for (int nt = 0; nt < 8; nt++) {
                int col = n0 + 8 * nt + 2 * tig;
                float2 v = make_float2(acc[mt][nt][2] + b2s[col],
                                       acc[mt][nt][3] + b2s[col + 1]);
                *(float2*)(o + col) = v;
            }
        }
    }
}

// ---------------- scatter cell outputs to node sums + counts ----------------
__global__ void scatter_cell_kernel(const float* __restrict__ cell_out,
                                    const int*   __restrict__ face,
                                    float* __restrict__ node_out) {
    int w    = (blockIdx.x * blockDim.x + threadIdx.x) >> 5;
    int lane = threadIdx.x & 31;
    if (w >= THREEC) return;
    int node = face[w];
    int c = w;
    if (c >= NCELLS) c -= NCELLS;
    if (c >= NCELLS) c -= NCELLS;

    float4 v = __ldg(((const float4*)cell_out) + (size_t)c * 32 + lane);
    float* dst = node_out + (size_t)node * DIM + lane * 4;
    asm volatile("red.global.add.v4.f32 [%0], {%1,%2,%3,%4};"
                 :: "l"(dst), "f"(v.x), "f"(v.y), "f"(v.z), "f"(v.w)
                 : "memory");
    if (lane == 0) atomicAdd(&g_counts[node], 1.f);
}

__global__ void finalize_kernel(float* __restrict__ node_out) {
    int i = blockIdx.x * 256 + threadIdx.x;
    if (i >= NNODES * DIM / 4) return;
    float inv = 1.f / fmaxf(g_counts[i >> 5], 1.f);
    float4 v = ((float4*)node_out)[i];
    v.x *= inv; v.y *= inv; v.z *= inv; v.w *= inv;
    ((float4*)node_out)[i] = v;
}

// ---------------- launch ----------------
extern "C" void kernel_launch(void* const* d_in, const int* in_sizes, int n_in,
                              void* d_out, int out_size) {
    const float* cell_attr  = (const float*)d_in[0];
    const float* edge_attr  = (const float*)d_in[1];
    const float* node_emb   = (const float*)d_in[2];
    const int*   edge_index = (const int*)d_in[3];
    const int*   face       = (const int*)d_in[4];
    const float* W1 = (const float*)d_in[5];
    const float* b1 = (const float*)d_in[6];
    const float* W2 = (const float*)d_in[7];
    const float* b2 = (const float*)d_in[8];

    float* out      = (float*)d_out;
    float* cell_out = out;                         // [NCELLS, 128]
    float* node_out = out + (size_t)NCELLS * DIM;  // [NNODES, 128]

    cudaFuncSetAttribute(mlp_mma_kernel,
                         cudaFuncAttributeMaxDynamicSharedMemorySize, MLP_SMEM);

    zero_kernel<<<50000, 256>>>(node_out);
    attn_kernel<<<37500, 256>>>(edge_attr, node_emb, edge_index);
    normalize_kernel<<<12500, 256>>>();
    mlp_mma_kernel<<<1563, 256, MLP_SMEM>>>(cell_attr, face, W1, b1, W2, b2, cell_out);
    scatter_cell_kernel<<<75000, 256>>>(cell_out, face, node_out);
    finalize_kernel<<<12500, 256>>>(node_out);
}

// round 4
// speedup vs baseline: 1.6725x; 1.0443x over previous
#include <cuda_runtime.h>
#include <math.h>
#include <cstdint>

#define NNODES 100000
#define NCELLS 200000
#define NEDGES 300000
#define DIM 128
#define THREEC (3*NCELLS)

// ---------------- scratch (static device globals: allocation-free) ----------
__device__ float g_nodesum[NNODES];
__device__ float g_counts[NNODES];
__device__ float g_nodeagg[(size_t)NNODES * DIM];

// ---------------- helpers ----------------
__device__ __forceinline__ uint32_t rna(float x) {
    uint32_t u; asm("cvt.rna.tf32.f32 %0, %1;" : "=r"(u) : "f"(x)); return u;
}
__device__ __forceinline__ float rnaf(float x) { return __uint_as_float(rna(x)); }

__device__ __forceinline__ void mma8(float c[4], const uint32_t a[4], const uint32_t b[2]) {
    asm volatile("mma.sync.aligned.m16n8k8.row.col.f32.tf32.tf32.f32 "
        "{%0,%1,%2,%3}, {%4,%5,%6,%7}, {%8,%9}, {%0,%1,%2,%3};"
        : "+f"(c[0]), "+f"(c[1]), "+f"(c[2]), "+f"(c[3])
        : "r"(a[0]), "r"(a[1]), "r"(a[2]), "r"(a[3]), "r"(b[0]), "r"(b[1]));
}

// ---------------- zero init ----------------
__global__ void zero_kernel(float* __restrict__ node_out) {
    int i = blockIdx.x * 256 + threadIdx.x;
    if (i < NNODES * DIM) { g_nodeagg[i] = 0.f; node_out[i] = 0.f; }
    if (i < NNODES)       { g_nodesum[i] = 0.f; g_counts[i] = 0.f; }
}

// ---------------- fused attention: one warp per EDGE, both directions -------
__global__ void attn_kernel(const float* __restrict__ edge_attr,
                            const float* __restrict__ node_emb,
                            const int*   __restrict__ edge_index) {
    int e    = (blockIdx.x * blockDim.x + threadIdx.x) >> 5;
    int lane = threadIdx.x & 31;
    if (e >= NEDGES) return;
    int s = __ldg(edge_index + e);
    int r = __ldg(edge_index + NEDGES + e);

    float4 a  = __ldg(((const float4*)edge_attr) + (size_t)e * 32 + lane);
    float4 bs = __ldg(((const float4*)node_emb)  + (size_t)s * 32 + lane);
    float4 br = __ldg(((const float4*)node_emb)  + (size_t)r * 32 + lane);
    float ds = a.x * bs.x + a.y * bs.y + a.z * bs.z + a.w * bs.w;
    float dr = a.x * br.x + a.y * br.y + a.z * br.z + a.w * br.w;
    #pragma unroll
    for (int off = 16; off > 0; off >>= 1) {
        ds += __shfl_xor_sync(0xffffffffu, ds, off);
        dr += __shfl_xor_sync(0xffffffffu, dr, off);
    }
    float es = expf(ds * 0.08838834764831845f);   // logits bounded, no max-shift
    float er = expf(dr * 0.08838834764831845f);

    float* dstr = g_nodeagg + (size_t)r * DIM + lane * 4;
    asm volatile("red.global.add.v4.f32 [%0], {%1,%2,%3,%4};"
                 :: "l"(dstr), "f"(a.x * er), "f"(a.y * er), "f"(a.z * er), "f"(a.w * er)
                 : "memory");
    float* dsts = g_nodeagg + (size_t)s * DIM + lane * 4;
    asm volatile("red.global.add.v4.f32 [%0], {%1,%2,%3,%4};"
                 :: "l"(dsts), "f"(a.x * es), "f"(a.y * es), "f"(a.z * es), "f"(a.w * es)
                 : "memory");
    if (lane == 0) atomicAdd(&g_nodesum[r], er);
    if (lane == 1) atomicAdd(&g_nodesum[s], es);
}

__global__ void normalize_kernel() {
    int i = blockIdx.x * 256 + threadIdx.x;
    if (i >= NNODES * 32) return;
    float sum = g_nodesum[i >> 5];
    float inv = (sum > 0.f) ? (1.f / sum) : 0.f;
    float4 v = ((float4*)g_nodeagg)[i];
    v.x *= inv; v.y *= inv; v.z *= inv; v.w *= inv;
    ((float4*)g_nodeagg)[i] = v;
}

// ============================================================================
// fused MLP on tf32 mma.sync, 512 threads (16 warps, warp tile 32x32), BK=32
// SMEM tiles k-major, LDP=136 -> conflict-free fragment loads
// ============================================================================
#define LDP 136
#define SA_OFF 0
#define SB_OFF (32*LDP)
#define SH_OFF (64*LDP)
#define B1_OFF (SH_OFF + 128*LDP)
#define B2_OFF (B1_OFF + 128)
#define SF_OFF (B2_OFF + 128)
#define SMEM_FLOATS (SF_OFF + 384)
#define MLP_SMEM (SMEM_FLOATS * 4)

__global__ __launch_bounds__(512, 1)
void mlp_mma_kernel(const float* __restrict__ cell_attr, const int* __restrict__ face,
                    const float* __restrict__ W1, const float* __restrict__ b1,
                    const float* __restrict__ W2, const float* __restrict__ b2,
                    float* __restrict__ out) {
    extern __shared__ float sm[];
    float* sA  = sm + SA_OFF;
    float* sB  = sm + SB_OFF;
    float* sH  = sm + SH_OFF;
    float* b1s = sm + B1_OFF;
    float* b2s = sm + B2_OFF;
    int*   sF  = (int*)(sm + SF_OFF);

    const int tid  = threadIdx.x;
    const int wid  = tid >> 5, lane = tid & 31;
    const int g    = lane >> 2, tig = lane & 3;
    const int m0   = (wid & 3) * 32, n0 = (wid >> 2) * 32;
    const int rowBase = blockIdx.x * 128;

    if (tid < 128) {
        b1s[tid] = b1[tid]; b2s[tid] = b2[tid];
        int r = rowBase + tid;
        bool ok = r < NCELLS;
        sF[tid]       = ok ? face[r] : 0;
        sF[128 + tid] = ok ? face[NCELLS + r] : 0;
        sF[256 + tid] = ok ? face[2 * NCELLS + r] : 0;
    }
    // sF first used in fetchA(c>=4), which happens after __syncthreads below.

    float acc[2][4][4];
    #pragma unroll
    for (int mt = 0; mt < 2; mt++)
        #pragma unroll
        for (int nt = 0; nt < 4; nt++)
            #pragma unroll
            for (int q = 0; q < 4; q++) acc[mt][nt][q] = 0.f;

    float4 pa[2], pb[2];
    const float inv3 = 1.f / 3.f;

    // ---- A chunk (32 k wide): 1024 float4, 2 per thread ----
    auto fetchA = [&](int c) {
        #pragma unroll
        for (int h = 0; h < 2; h++) {
            int j = tid + h * 512;               // [0,1024)
            int m = j >> 3, kq = (j & 7) * 4;    // row, k-quad base within chunk
            float4 v = make_float4(0.f, 0.f, 0.f, 0.f);
            int r = rowBase + m;
            if (r < NCELLS) {
                if (c < 4) {
                    v = __ldg((const float4*)(cell_attr + (size_t)r * 128 + c * 32 + kq));
                } else {
                    int gk = (c - 4) * 32 + kq;
                    float4 a0 = __ldg((const float4*)(g_nodeagg + (size_t)sF[m]       * 128 + gk));
                    float4 a1 = __ldg((const float4*)(g_nodeagg + (size_t)sF[128 + m] * 128 + gk));
                    float4 a2 = __ldg((const float4*)(g_nodeagg + (size_t)sF[256 + m] * 128 + gk));
                    v.x = (a0.x + a1.x + a2.x) * inv3;
                    v.y = (a0.y + a1.y + a2.y) * inv3;
                    v.z = (a0.z + a1.z + a2.z) * inv3;
                    v.w = (a0.w + a1.w + a2.w) * inv3;
                }
            }
            pa[h] = v;
        }
    };
    auto storeA = [&]() {
        #pragma unroll
        for (int h = 0; h < 2; h++) {
            int j = tid + h * 512;
            int m = j >> 3, kq = (j & 7) * 4;
            sA[(kq + 0) * LDP + m] = rnaf(pa[h].x);
            sA[(kq + 1) * LDP + m] = rnaf(pa[h].y);
            sA[(kq + 2) * LDP + m] = rnaf(pa[h].z);
            sA[(kq + 3) * LDP + m] = rnaf(pa[h].w);
        }
    };
    auto fetchB = [&](const float* W, int c) {
        #pragma unroll
        for (int h = 0; h < 2; h++) {
            int j = tid + h * 512;               // [32k x 128n] float4s
            int k = j >> 5, n4 = (j & 31) * 4;
            pb[h] = __ldg((const float4*)(W + (size_t)(c * 32 + k) * 128 + n4));
        }
    };
    auto storeB = [&]() {
        #pragma unroll
        for (int h = 0; h < 2; h++) {
            int j = tid + h * 512;
            int k = j >> 5, n4 = (j & 31) * 4;
            float4 v;
            v.x = rnaf(pb[h].x); v.y = rnaf(pb[h].y);
            v.z = rnaf(pb[h].z); v.w = rnaf(pb[h].w);
            *(float4*)(sB + k * LDP + n4) = v;
        }
    };
    auto mmastep = [&](const float* Abase) {
        #pragma unroll
        for (int k0 = 0; k0 < 32; k0 += 8) {
            const float* ar = Abase + k0 * LDP;
            const float* br = sB + k0 * LDP;
            uint32_t af[2][4], bf[4][2];
            #pragma unroll
            for (int mt = 0; mt < 2; mt++) {
                int mm = m0 + 16 * mt + g;
                af[mt][0] = __float_as_uint(ar[tig * LDP + mm]);
                af[mt][1] = __float_as_uint(ar[tig * LDP + mm + 8]);
                af[mt][2] = __float_as_uint(ar[(tig + 4) * LDP + mm]);
                af[mt][3] = __float_as_uint(ar[(tig + 4) * LDP + mm + 8]);
            }
            #pragma unroll
            for (int nt = 0; nt < 4; nt++) {
                int nn = n0 + 8 * nt + g;
                bf[nt][0] = __float_as_uint(br[tig * LDP + nn]);
                bf[nt][1] = __float_as_uint(br[(tig + 4) * LDP + nn]);
            }
            #pragma unroll
            for (int mt = 0; mt < 2; mt++)
                #pragma unroll
                for (int nt = 0; nt < 4; nt++)
                    mma8(acc[mt][nt], af[mt], bf[nt]);
        }
    };

    // -------- GEMM1: concat(cell_attr, cell_agg)[128x256] @ W1 --------
    fetchA(0); fetchB(W1, 0);
    for (int c = 0; c < 8; c++) {
        storeA(); storeB();
        __syncthreads();
        if (c < 7) { fetchA(c + 1); fetchB(W1, c + 1); }
        mmastep(sA);
        __syncthreads();
    }

    // -------- epilogue 1: h = relu(D1 + b1) -> sH (k-major, tf32-rounded) ------
    #pragma unroll
    for (int mt = 0; mt < 2; mt++) {
        int row = m0 + 16 * mt + g;
        #pragma unroll
        for (int nt = 0; nt < 4; nt++) {
            int col = n0 + 8 * nt + 2 * tig;
            float bb0 = b1s[col], bb1 = b1s[col + 1];
            sH[col * LDP + row]           = rnaf(fmaxf(acc[mt][nt][0] + bb0, 0.f));
            sH[(col + 1) * LDP + row]     = rnaf(fmaxf(acc[mt][nt][1] + bb1, 0.f));
            sH[col * LDP + row + 8]       = rnaf(fmaxf(acc[mt][nt][2] + bb0, 0.f));
            sH[(col + 1) * LDP + row + 8] = rnaf(fmaxf(acc[mt][nt][3] + bb1, 0.f));
            acc[mt][nt][0] = 0.f; acc[mt][nt][1] = 0.f;
            acc[mt][nt][2] = 0.f; acc[mt][nt][3] = 0.f;
        }
    }
    __syncthreads();

    // -------- GEMM2: h[128x128] @ W2 --------
    fetchB(W2, 0);
    for (int c = 0; c < 4; c++) {
        storeB();
        __syncthreads();
        if (c < 3) fetchB(W2, c + 1);
        mmastep(sH + c * 32 * LDP);
        __syncthreads();
    }

    // -------- epilogue 2: out = D2 + b2 --------
    #pragma unroll
    for (int mt = 0; mt < 2; mt++) {
        int row = m0 + 16 * mt + g;
        if (rowBase + row < NCELLS) {
            float* o = out + (size_t)(rowBase + row) * 128;
            #pragma unroll
            for (int nt = 0; nt < 4; nt++) {
                int col = n0 + 8 * nt + 2 * tig;
                float2 v = make_float2(acc[mt][nt][0] + b2s[col],
                                       acc[mt][nt][1] + b2s[col + 1]);
                *(float2*)(o + col) = v;
            }
        }
        if (rowBase + row + 8 < NCELLS) {
            float* o = out + (size_t)(rowBase + row + 8) * 128;
            #pragma unroll
            for (int nt = 0; nt < 4; nt++) {
                int col = n0 + 8 * nt + 2 * tig;
                float2 v = make_float2(acc[mt][nt][2] + b2s[col],
                                       acc[mt][nt][3] + b2s[col + 1]);
                *(float2*)(o + col) = v;
            }
        }
    }
}

// ---------------- scatter cell outputs to node sums + counts ----------------
__global__ void scatter_cell_kernel(const float* __restrict__ cell_out,
                                    const int*   __restrict__ face,
                                    float* __restrict__ node_out) {
    int w    = (blockIdx.x * blockDim.x + threadIdx.x) >> 5;
    int lane = threadIdx.x & 31;
    if (w >= THREEC) return;
    int node = face[w];
    int c = w;
    if (c >= NCELLS) c -= NCELLS;
    if (c >= NCELLS) c -= NCELLS;

    float4 v = __ldg(((const float4*)cell_out) + (size_t)c * 32 + lane);
    float* dst = node_out + (size_t)node * DIM + lane * 4;
    asm volatile("red.global.add.v4.f32 [%0], {%1,%2,%3,%4};"
                 :: "l"(dst), "f"(v.x), "f"(v.y), "f"(v.z), "f"(v.w)
                 : "memory");
    if (lane == 0) atomicAdd(&g_counts[node], 1.f);
}

__global__ void finalize_kernel(float* __restrict__ node_out) {
    int i = blockIdx.x * 256 + threadIdx.x;
    if (i >= NNODES * DIM / 4) return;
    float inv = 1.f / fmaxf(g_counts[i >> 5], 1.f);
    float4 v = ((float4*)node_out)[i];
    v.x *= inv; v.y *= inv; v.z *= inv; v.w *= inv;
    ((float4*)node_out)[i] = v;
}

// ---------------- launch ----------------
extern "C" void kernel_launch(void* const* d_in, const int* in_sizes, int n_in,
                              void* d_out, int out_size) {
    const float* cell_attr  = (const float*)d_in[0];
    const float* edge_attr  = (const float*)d_in[1];
    const float* node_emb   = (const float*)d_in[2];
    const int*   edge_index = (const int*)d_in[3];
    const int*   face       = (const int*)d_in[4];
    const float* W1 = (const float*)d_in[5];
    const float* b1 = (const float*)d_in[6];
    const float* W2 = (const float*)d_in[7];
    const float* b2 = (const float*)d_in[8];

    float* out      = (float*)d_out;
    float* cell_out = out;
    float* node_out = out + (size_t)NCELLS * DIM;

    cudaFuncSetAttribute(mlp_mma_kernel,
                         cudaFuncAttributeMaxDynamicSharedMemorySize, MLP_SMEM);

    zero_kernel<<<50000, 256>>>(node_out);
    attn_kernel<<<37500, 256>>>(edge_attr, node_emb, edge_index);
    normalize_kernel<<<12500, 256>>>();
    mlp_mma_kernel<<<1563, 512, MLP_SMEM>>>(cell_attr, face, W1, b1, W2, b2, cell_out);
    scatter_cell_kernel<<<75000, 256>>>(cell_out, face, node_out);
    finalize_kernel<<<12500, 256>>>(node_out);
}

// round 5
// speedup vs baseline: 1.6845x; 1.0071x over previous
#include <cuda_runtime.h>
#include <math.h>
#include <cstdint>

#define NNODES 100000
#define NCELLS 200000
#define NEDGES 300000
#define DIM 128
#define THREEC (3*NCELLS)

// ---------------- scratch (static device globals: allocation-free) ----------
__device__ float g_nodesum[NNODES];
__device__ float g_counts[NNODES];
__device__ float g_nodeagg[(size_t)NNODES * DIM];

// ---------------- helpers ----------------
__device__ __forceinline__ uint32_t rna(float x) {
    uint32_t u; asm("cvt.rna.tf32.f32 %0, %1;" : "=r"(u) : "f"(x)); return u;
}
__device__ __forceinline__ float rnaf(float x) { return __uint_as_float(rna(x)); }

__device__ __forceinline__ void mma8(float c[4], const uint32_t a[4], const uint32_t b[2]) {
    asm volatile("mma.sync.aligned.m16n8k8.row.col.f32.tf32.tf32.f32 "
        "{%0,%1,%2,%3}, {%4,%5,%6,%7}, {%8,%9}, {%0,%1,%2,%3};"
        : "+f"(c[0]), "+f"(c[1]), "+f"(c[2]), "+f"(c[3])
        : "r"(a[0]), "r"(a[1]), "r"(a[2]), "r"(a[3]), "r"(b[0]), "r"(b[1]));
}

// ---------------- zero init ----------------
__global__ void zero_kernel(float* __restrict__ node_out) {
    int i = blockIdx.x * 256 + threadIdx.x;
    if (i < NNODES * DIM) { g_nodeagg[i] = 0.f; node_out[i] = 0.f; }
    if (i < NNODES)       { g_nodesum[i] = 0.f; g_counts[i] = 0.f; }
}

// ---------------- fused attention: one warp per EDGE, both directions -------
__global__ void attn_kernel(const float* __restrict__ edge_attr,
                            const float* __restrict__ node_emb,
                            const int*   __restrict__ edge_index) {
    int e    = (blockIdx.x * blockDim.x + threadIdx.x) >> 5;
    int lane = threadIdx.x & 31;
    if (e >= NEDGES) return;
    int s = __ldg(edge_index + e);
    int r = __ldg(edge_index + NEDGES + e);

    float4 a  = __ldg(((const float4*)edge_attr) + (size_t)e * 32 + lane);
    float4 bs = __ldg(((const float4*)node_emb)  + (size_t)s * 32 + lane);
    float4 br = __ldg(((const float4*)node_emb)  + (size_t)r * 32 + lane);
    float ds = a.x * bs.x + a.y * bs.y + a.z * bs.z + a.w * bs.w;
    float dr = a.x * br.x + a.y * br.y + a.z * br.z + a.w * br.w;
    #pragma unroll
    for (int off = 16; off > 0; off >>= 1) {
        ds += __shfl_xor_sync(0xffffffffu, ds, off);
        dr += __shfl_xor_sync(0xffffffffu, dr, off);
    }
    float es = expf(ds * 0.08838834764831845f);   // logits bounded, no max-shift
    float er = expf(dr * 0.08838834764831845f);

    float* dstr = g_nodeagg + (size_t)r * DIM + lane * 4;
    asm volatile("red.global.add.v4.f32 [%0], {%1,%2,%3,%4};"
                 :: "l"(dstr), "f"(a.x * er), "f"(a.y * er), "f"(a.z * er), "f"(a.w * er)
                 : "memory");
    float* dsts = g_nodeagg + (size_t)s * DIM + lane * 4;
    asm volatile("red.global.add.v4.f32 [%0], {%1,%2,%3,%4};"
                 :: "l"(dsts), "f"(a.x * es), "f"(a.y * es), "f"(a.z * es), "f"(a.w * es)
                 : "memory");
    if (lane == 0) atomicAdd(&g_nodesum[r], er);
    if (lane == 1) atomicAdd(&g_nodesum[s], es);
}

__global__ void normalize_kernel() {
    int i = blockIdx.x * 256 + threadIdx.x;
    if (i >= NNODES * 32) return;
    float sum = g_nodesum[i >> 5];
    float inv = (sum > 0.f) ? (1.f / sum) : 0.f;
    float4 v = ((float4*)g_nodeagg)[i];
    v.x *= inv; v.y *= inv; v.z *= inv; v.w *= inv;
    ((float4*)g_nodeagg)[i] = v;
}

// ============================================================================
// fused MLP on tf32 mma.sync, 512 threads (16 warps, warp tile 32x32), BK=32
// SMEM tiles k-major, LDP=136 -> conflict-free fragment loads
// ============================================================================
#define LDP 136
#define SA_OFF 0
#define SB_OFF (32*LDP)
#define SH_OFF (64*LDP)
#define B1_OFF (SH_OFF + 128*LDP)
#define B2_OFF (B1_OFF + 128)
#define SF_OFF (B2_OFF + 128)
#define SMEM_FLOATS (SF_OFF + 384)
#define MLP_SMEM (SMEM_FLOATS * 4)

__global__ __launch_bounds__(512, 1)
void mlp_mma_kernel(const float* __restrict__ cell_attr, const int* __restrict__ face,
                    const float* __restrict__ W1, const float* __restrict__ b1,
                    const float* __restrict__ W2, const float* __restrict__ b2,
                    float* __restrict__ out) {
    extern __shared__ float sm[];
    float* sA  = sm + SA_OFF;
    float* sB  = sm + SB_OFF;
    float* sH  = sm + SH_OFF;
    float* b1s = sm + B1_OFF;
    float* b2s = sm + B2_OFF;
    int*   sF  = (int*)(sm + SF_OFF);

    const int tid  = threadIdx.x;
    const int wid  = tid >> 5, lane = tid & 31;
    const int g    = lane >> 2, tig = lane & 3;
    const int m0   = (wid & 3) * 32, n0 = (wid >> 2) * 32;
    const int rowBase = blockIdx.x * 128;

    if (tid < 128) {
        b1s[tid] = b1[tid]; b2s[tid] = b2[tid];
        int r = rowBase + tid;
        bool ok = r < NCELLS;
        sF[tid]       = ok ? face[r] : 0;
        sF[128 + tid] = ok ? face[NCELLS + r] : 0;
        sF[256 + tid] = ok ? face[2 * NCELLS + r] : 0;
    }
    // sF first used in fetchA(c>=4), which happens after __syncthreads below.

    float acc[2][4][4];
    #pragma unroll
    for (int mt = 0; mt < 2; mt++)
        #pragma unroll
        for (int nt = 0; nt < 4; nt++)
            #pragma unroll
            for (int q = 0; q < 4; q++) acc[mt][nt][q] = 0.f;

    float4 pa[2], pb[2];
    const float inv3 = 1.f / 3.f;

    // ---- A chunk (32 k wide): 1024 float4, 2 per thread ----
    auto fetchA = [&](int c) {
        #pragma unroll
        for (int h = 0; h < 2; h++) {
            int j = tid + h * 512;               // [0,1024)
            int m = j >> 3, kq = (j & 7) * 4;    // row, k-quad base within chunk
            float4 v = make_float4(0.f, 0.f, 0.f, 0.f);
            int r = rowBase + m;
            if (r < NCELLS) {
                if (c < 4) {
                    v = __ldg((const float4*)(cell_attr + (size_t)r * 128 + c * 32 + kq));
                } else {
                    int gk = (c - 4) * 32 + kq;
                    float4 a0 = __ldg((const float4*)(g_nodeagg + (size_t)sF[m]       * 128 + gk));
                    float4 a1 = __ldg((const float4*)(g_nodeagg + (size_t)sF[128 + m] * 128 + gk));
                    float4 a2 = __ldg((const float4*)(g_nodeagg + (size_t)sF[256 + m] * 128 + gk));
                    v.x = (a0.x + a1.x + a2.x) * inv3;
                    v.y = (a0.y + a1.y + a2.y) * inv3;
                    v.z = (a0.z + a1.z + a2.z) * inv3;
                    v.w = (a0.w + a1.w + a2.w) * inv3;
                }
            }
            pa[h] = v;
        }
    };
    auto storeA = [&]() {
        #pragma unroll
        for (int h = 0; h < 2; h++) {
            int j = tid + h * 512;
            int m = j >> 3, kq = (j & 7) * 4;
            sA[(kq + 0) * LDP + m] = rnaf(pa[h].x);
            sA[(kq + 1) * LDP + m] = rnaf(pa[h].y);
            sA[(kq + 2) * LDP + m] = rnaf(pa[h].z);
            sA[(kq + 3) * LDP + m] = rnaf(pa[h].w);
        }
    };
    auto fetchB = [&](const float* W, int c) {
        #pragma unroll
        for (int h = 0; h < 2; h++) {
            int j = tid + h * 512;               // [32k x 128n] float4s
            int k = j >> 5, n4 = (j & 31) * 4;
            pb[h] = __ldg((const float4*)(W + (size_t)(c * 32 + k) * 128 + n4));
        }
    };
    auto storeB = [&]() {
        #pragma unroll
        for (int h = 0; h < 2; h++) {
            int j = tid + h * 512;
            int k = j >> 5, n4 = (j & 31) * 4;
            float4 v;
            v.x = rnaf(pb[h].x); v.y = rnaf(pb[h].y);
            v.z = rnaf(pb[h].z); v.w = rnaf(pb[h].w);
            *(float4*)(sB + k * LDP + n4) = v;
        }
    };
    auto mmastep = [&](const float* Abase) {
        #pragma unroll
        for (int k0 = 0; k0 < 32; k0 += 8) {
            const float* ar = Abase + k0 * LDP;
            const float* br = sB + k0 * LDP;
            uint32_t af[2][4], bf[4][2];
            #pragma unroll
            for (int mt = 0; mt < 2; mt++) {
                int mm = m0 + 16 * mt + g;
                af[mt][0] = __float_as_uint(ar[tig * LDP + mm]);
                af[mt][1] = __float_as_uint(ar[tig * LDP + mm + 8]);
                af[mt][2] = __float_as_uint(ar[(tig + 4) * LDP + mm]);
                af[mt][3] = __float_as_uint(ar[(tig + 4) * LDP + mm + 8]);
            }
            #pragma unroll
            for (int nt = 0; nt < 4; nt++) {
                int nn = n0 + 8 * nt + g;
                bf[nt][0] = __float_as_uint(br[tig * LDP + nn]);
                bf[nt][1] = __float_as_uint(br[(tig + 4) * LDP + nn]);
            }
            #pragma unroll
            for (int mt = 0; mt < 2; mt++)
                #pragma unroll
                for (int nt = 0; nt < 4; nt++)
                    mma8(acc[mt][nt], af[mt], bf[nt]);
        }
    };

    // -------- GEMM1: concat(cell_attr, cell_agg)[128x256] @ W1 --------
    fetchA(0); fetchB(W1, 0);
    for (int c = 0; c < 8; c++) {
        storeA(); storeB();
        __syncthreads();
        if (c < 7) { fetchA(c + 1); fetchB(W1, c + 1); }
        mmastep(sA);
        __syncthreads();
    }

    // -------- epilogue 1: h = relu(D1 + b1) -> sH (k-major, tf32-rounded) ------
    #pragma unroll
    for (int mt = 0; mt < 2; mt++) {
        int row = m0 + 16 * mt + g;
        #pragma unroll
        for (int nt = 0; nt < 4; nt++) {
            int col = n0 + 8 * nt + 2 * tig;
            float bb0 = b1s[col], bb1 = b1s[col + 1];
            sH[col * LDP + row]           = rnaf(fmaxf(acc[mt][nt][0] + bb0, 0.f));
            sH[(col + 1) * LDP + row]     = rnaf(fmaxf(acc[mt][nt][1] + bb1, 0.f));
            sH[col * LDP + row + 8]       = rnaf(fmaxf(acc[mt][nt][2] + bb0, 0.f));
            sH[(col + 1) * LDP + row + 8] = rnaf(fmaxf(acc[mt][nt][3] + bb1, 0.f));
            acc[mt][nt][0] = 0.f; acc[mt][nt][1] = 0.f;
            acc[mt][nt][2] = 0.f; acc[mt][nt][3] = 0.f;
        }
    }
    __syncthreads();

    // -------- GEMM2: h[128x128] @ W2 --------
    fetchB(W2, 0);
    for (int c = 0; c < 4; c++) {
        storeB();
        __syncthreads();
        if (c < 3) fetchB(W2, c + 1);
        mmastep(sH + c * 32 * LDP);
        __syncthreads();
    }

    // -------- epilogue 2: out = D2 + b2 --------
    #pragma unroll
    for (int mt = 0; mt < 2; mt++) {
        int row = m0 + 16 * mt + g;
        if (rowBase + row < NCELLS) {
            float* o = out + (size_t)(rowBase + row) * 128;
            #pragma unroll
            for (int nt = 0; nt < 4; nt++) {
                int col = n0 + 8 * nt + 2 * tig;
                float2 v = make_float2(acc[mt][nt][0] + b2s[col],
                                       acc[mt][nt][1] + b2s[col + 1]);
                *(float2*)(o + col) = v;
            }
        }
        if (rowBase + row + 8 < NCELLS) {
            float* o = out + (size_t)(rowBase + row + 8) * 128;
            #pragma unroll
            for (int nt = 0; nt < 4; nt++) {
                int col = n0 + 8 * nt + 2 * tig;
                float2 v = make_float2(acc[mt][nt][2] + b2s[col],
                                       acc[mt][nt][3] + b2s[col + 1]);
                *(float2*)(o + col) = v;
            }
        }
    }
}

// ---------------- scatter cell outputs to node sums + counts ----------------
__global__ void scatter_cell_kernel(const float* __restrict__ cell_out,
                                    const int*   __restrict__ face,
                                    float* __restrict__ node_out) {
    int w    = (blockIdx.x * blockDim.x + threadIdx.x) >> 5;
    int lane = threadIdx.x & 31;
    if (w >= THREEC) return;
    int node = face[w];
    int c = w;
    if (c >= NCELLS) c -= NCELLS;
    if (c >= NCELLS) c -= NCELLS;

    float4 v = __ldg(((const float4*)cell_out) + (size_t)c * 32 + lane);
    float* dst = node_out + (size_t)node * DIM + lane * 4;
    asm volatile("red.global.add.v4.f32 [%0], {%1,%2,%3,%4};"
                 :: "l"(dst), "f"(v.x), "f"(v.y), "f"(v.z), "f"(v.w)
                 : "memory");
    if (lane == 0) atomicAdd(&g_counts[node], 1.f);
}

__global__ void finalize_kernel(float* __restrict__ node_out) {
    int i = blockIdx.x * 256 + threadIdx.x;
    if (i >= NNODES * DIM / 4) return;
    float inv = 1.f / fmaxf(g_counts[i >> 5], 1.f);
    float4 v = ((float4*)node_out)[i];
    v.x *= inv; v.y *= inv; v.z *= inv; v.w *= inv;
    ((float4*)node_out)[i] = v;
}

// ---------------- launch ----------------
extern "C" void kernel_launch(void* const* d_in, const int* in_sizes, int n_in,
                              void* d_out, int out_size) {
    const float* cell_attr  = (const float*)d_in[0];
    const float* edge_attr  = (const float*)d_in[1];
    const float* node_emb   = (const float*)d_in[2];
    const int*   edge_index = (const int*)d_in[3];
    const int*   face       = (const int*)d_in[4];
    const float* W1 = (const float*)d_in[5];
    const float* b1 = (const float*)d_in[6];
    const float* W2 = (const float*)d_in[7];
    const float* b2 = (const float*)d_in[8];

    float* out      = (float*)d_out;
    float* cell_out = out;
    float* node_out = out + (size_t)NCELLS * DIM;

    cudaFuncSetAttribute(mlp_mma_kernel,
                         cudaFuncAttributeMaxDynamicSharedMemorySize, MLP_SMEM);

    zero_kernel<<<50000, 256>>>(node_out);
    attn_kernel<<<37500, 256>>>(edge_attr, node_emb, edge_index);
    normalize_kernel<<<12500, 256>>>();
    mlp_mma_kernel<<<1563, 512, MLP_SMEM>>>(cell_attr, face, W1, b1, W2, b2, cell_out);
    scatter_cell_kernel<<<75000, 256>>>(cell_out, face, node_out);
    finalize_kernel<<<12500, 256>>>(node_out);
}

// round 6
// speedup vs baseline: 1.6863x; 1.0011x over previous
#include <cuda_runtime.h>
#include <math.h>
#include <cstdint>

#define NNODES 100000
#define NCELLS 200000
#define NEDGES 300000
#define DIM 128
#define THREEC (3*NCELLS)

// ---------------- scratch (static device globals: allocation-free) ----------
__device__ float g_nodesum[NNODES];
__device__ float g_counts[NNODES];
__device__ float g_nodeagg[(size_t)NNODES * DIM];

// ---------------- helpers ----------------
__device__ __forceinline__ uint32_t rna(float x) {
    uint32_t u; asm("cvt.rna.tf32.f32 %0, %1;" : "=r"(u) : "f"(x)); return u;
}
__device__ __forceinline__ float rnaf(float x) { return __uint_as_float(rna(x)); }

__device__ __forceinline__ void mma8(float c[4], const uint32_t a[4], const uint32_t b[2]) {
    asm volatile("mma.sync.aligned.m16n8k8.row.col.f32.tf32.tf32.f32 "
        "{%0,%1,%2,%3}, {%4,%5,%6,%7}, {%8,%9}, {%0,%1,%2,%3};"
        : "+f"(c[0]), "+f"(c[1]), "+f"(c[2]), "+f"(c[3])
        : "r"(a[0]), "r"(a[1]), "r"(a[2]), "r"(a[3]), "r"(b[0]), "r"(b[1]));
}

// ---------------- zero init ----------------
__global__ void zero_kernel(float* __restrict__ node_out) {
    int i = blockIdx.x * 256 + threadIdx.x;
    if (i < NNODES * DIM) { g_nodeagg[i] = 0.f; node_out[i] = 0.f; }
    if (i < NNODES)       { g_nodesum[i] = 0.f; g_counts[i] = 0.f; }
}

// ---------------- fused attention: one warp per EDGE, both directions -------
__global__ void attn_kernel(const float* __restrict__ edge_attr,
                            const float* __restrict__ node_emb,
                            const int*   __restrict__ edge_index) {
    int e    = (blockIdx.x * blockDim.x + threadIdx.x) >> 5;
    int lane = threadIdx.x & 31;
    if (e >= NEDGES) return;
    int s = __ldg(edge_index + e);
    int r = __ldg(edge_index + NEDGES + e);

    float4 a  = __ldg(((const float4*)edge_attr) + (size_t)e * 32 + lane);
    float4 bs = __ldg(((const float4*)node_emb)  + (size_t)s * 32 + lane);
    float4 br = __ldg(((const float4*)node_emb)  + (size_t)r * 32 + lane);
    float ds = a.x * bs.x + a.y * bs.y + a.z * bs.z + a.w * bs.w;
    float dr = a.x * br.x + a.y * br.y + a.z * br.z + a.w * br.w;
    #pragma unroll
    for (int off = 16; off > 0; off >>= 1) {
        ds += __shfl_xor_sync(0xffffffffu, ds, off);
        dr += __shfl_xor_sync(0xffffffffu, dr, off);
    }
    float es = expf(ds * 0.08838834764831845f);   // logits bounded, no max-shift
    float er = expf(dr * 0.08838834764831845f);

    float* dstr = g_nodeagg + (size_t)r * DIM + lane * 4;
    asm volatile("red.global.add.v4.f32 [%0], {%1,%2,%3,%4};"
                 :: "l"(dstr), "f"(a.x * er), "f"(a.y * er), "f"(a.z * er), "f"(a.w * er)
                 : "memory");
    float* dsts = g_nodeagg + (size_t)s * DIM + lane * 4;
    asm volatile("red.global.add.v4.f32 [%0], {%1,%2,%3,%4};"
                 :: "l"(dsts), "f"(a.x * es), "f"(a.y * es), "f"(a.z * es), "f"(a.w * es)
                 : "memory");
    if (lane == 0) atomicAdd(&g_nodesum[r], er);
    if (lane == 1) atomicAdd(&g_nodesum[s], es);
}

__global__ void normalize_kernel() {
    int i = blockIdx.x * 256 + threadIdx.x;
    if (i >= NNODES * 32) return;
    float sum = g_nodesum[i >> 5];
    float inv = (sum > 0.f) ? (1.f / sum) : 0.f;
    float4 v = ((float4*)g_nodeagg)[i];
    v.x *= inv; v.y *= inv; v.z *= inv; v.w *= inv;
    ((float4*)g_nodeagg)[i] = v;
}

// ============================================================================
// fused MLP on tf32 mma.sync, 512 threads (16 warps, warp tile 32x32), BK=32
// SMEM tiles k-major, LDP=136 -> conflict-free fragment loads
// ============================================================================
#define LDP 136
#define SA_OFF 0
#define SB_OFF (32*LDP)
#define SH_OFF (64*LDP)
#define B1_OFF (SH_OFF + 128*LDP)
#define B2_OFF (B1_OFF + 128)
#define SF_OFF (B2_OFF + 128)
#define SMEM_FLOATS (SF_OFF + 384)
#define MLP_SMEM (SMEM_FLOATS * 4)

__global__ __launch_bounds__(512, 1)
void mlp_mma_kernel(const float* __restrict__ cell_attr, const int* __restrict__ face,
                    const float* __restrict__ W1, const float* __restrict__ b1,
                    const float* __restrict__ W2, const float* __restrict__ b2,
                    float* __restrict__ out) {
    extern __shared__ float sm[];
    float* sA  = sm + SA_OFF;
    float* sB  = sm + SB_OFF;
    float* sH  = sm + SH_OFF;
    float* b1s = sm + B1_OFF;
    float* b2s = sm + B2_OFF;
    int*   sF  = (int*)(sm + SF_OFF);

    const int tid  = threadIdx.x;
    const int wid  = tid >> 5, lane = tid & 31;
    const int g    = lane >> 2, tig = lane & 3;
    const int m0   = (wid & 3) * 32, n0 = (wid >> 2) * 32;
    const int rowBase = blockIdx.x * 128;

    if (tid < 128) {
        b1s[tid] = b1[tid]; b2s[tid] = b2[tid];
        int r = rowBase + tid;
        bool ok = r < NCELLS;
        sF[tid]       = ok ? face[r] : 0;
        sF[128 + tid] = ok ? face[NCELLS + r] : 0;
        sF[256 + tid] = ok ? face[2 * NCELLS + r] : 0;
    }
    // sF first used in fetchA(c>=4), which happens after __syncthreads below.

    float acc[2][4][4];
    #pragma unroll
    for (int mt = 0; mt < 2; mt++)
        #pragma unroll
        for (int nt = 0; nt < 4; nt++)
            #pragma unroll
            for (int q = 0; q < 4; q++) acc[mt][nt][q] = 0.f;

    float4 pa[2], pb[2];
    const float inv3 = 1.f / 3.f;

    // ---- A chunk (32 k wide): 1024 float4, 2 per thread ----
    auto fetchA = [&](int c) {
        #pragma unroll
        for (int h = 0; h < 2; h++) {
            int j = tid + h * 512;               // [0,1024)
            int m = j >> 3, kq = (j & 7) * 4;    // row, k-quad base within chunk
            float4 v = make_float4(0.f, 0.f, 0.f, 0.f);
            int r = rowBase + m;
            if (r < NCELLS) {
                if (c < 4) {
                    v = __ldg((const float4*)(cell_attr + (size_t)r * 128 + c * 32 + kq));
                } else {
                    int gk = (c - 4) * 32 + kq;
                    float4 a0 = __ldg((const float4*)(g_nodeagg + (size_t)sF[m]       * 128 + gk));
                    float4 a1 = __ldg((const float4*)(g_nodeagg + (size_t)sF[128 + m] * 128 + gk));
                    float4 a2 = __ldg((const float4*)(g_nodeagg + (size_t)sF[256 + m] * 128 + gk));
                    v.x = (a0.x + a1.x + a2.x) * inv3;
                    v.y = (a0.y + a1.y + a2.y) * inv3;
                    v.z = (a0.z + a1.z + a2.z) * inv3;
                    v.w = (a0.w + a1.w + a2.w) * inv3;
                }
            }
            pa[h] = v;
        }
    };
    auto storeA = [&]() {
        #pragma unroll
        for (int h = 0; h < 2; h++) {
            int j = tid + h * 512;
            int m = j >> 3, kq = (j & 7) * 4;
            sA[(kq + 0) * LDP + m] = rnaf(pa[h].x);
            sA[(kq + 1) * LDP + m] = rnaf(pa[h].y);
            sA[(kq + 2) * LDP + m] = rnaf(pa[h].z);
            sA[(kq + 3) * LDP + m] = rnaf(pa[h].w);
        }
    };
    auto fetchB = [&](const float* W, int c) {
        #pragma unroll
        for (int h = 0; h < 2; h++) {
            int j = tid + h * 512;               // [32k x 128n] float4s
            int k = j >> 5, n4 = (j & 31) * 4;
            pb[h] = __ldg((const float4*)(W + (size_t)(c * 32 + k) * 128 + n4));
        }
    };
    auto storeB = [&]() {
        #pragma unroll
        for (int h = 0; h < 2; h++) {
            int j = tid + h * 512;
            int k = j >> 5, n4 = (j & 31) * 4;
            float4 v;
            v.x = rnaf(pb[h].x); v.y = rnaf(pb[h].y);
            v.z = rnaf(pb[h].z); v.w = rnaf(pb[h].w);
            *(float4*)(sB + k * LDP + n4) = v;
        }
    };
    auto mmastep = [&](const float* Abase) {
        #pragma unroll
        for (int k0 = 0; k0 < 32; k0 += 8) {
            const float* ar = Abase + k0 * LDP;
            const float* br = sB + k0 * LDP;
            uint32_t af[2][4], bf[4][2];
            #pragma unroll
            for (int mt = 0; mt < 2; mt++) {
                int mm = m0 + 16 * mt + g;
                af[mt][0] = __float_as_uint(ar[tig * LDP + mm]);
                af[mt][1] = __float_as_uint(ar[tig * LDP + mm + 8]);
                af[mt][2] = __float_as_uint(ar[(tig + 4) * LDP + mm]);
                af[mt][3] = __float_as_uint(ar[(tig + 4) * LDP + mm + 8]);
            }
            #pragma unroll
            for (int nt = 0; nt < 4; nt++) {
                int nn = n0 + 8 * nt + g;
                bf[nt][0] = __float_as_uint(br[tig * LDP + nn]);
                bf[nt][1] = __float_as_uint(br[(tig + 4) * LDP + nn]);
            }
            #pragma unroll
            for (int mt = 0; mt < 2; mt++)
                #pragma unroll
                for (int nt = 0; nt < 4; nt++)
                    mma8(acc[mt][nt], af[mt], bf[nt]);
        }
    };

    // -------- GEMM1: concat(cell_attr, cell_agg)[128x256] @ W1 --------
    fetchA(0); fetchB(W1, 0);
    for (int c = 0; c < 8; c++) {
        storeA(); storeB();
        __syncthreads();
        if (c < 7) { fetchA(c + 1); fetchB(W1, c + 1); }
        mmastep(sA);
        __syncthreads();
    }

    // -------- epilogue 1: h = relu(D1 + b1) -> sH (k-major, tf32-rounded) ------
    #pragma unroll
    for (int mt = 0; mt < 2; mt++) {
        int row = m0 + 16 * mt + g;
        #pragma unroll
        for (int nt = 0; nt < 4; nt++) {
            int col = n0 + 8 * nt + 2 * tig;
            float bb0 = b1s[col], bb1 = b1s[col + 1];
            sH[col * LDP + row]           = rnaf(fmaxf(acc[mt][nt][0] + bb0, 0.f));
            sH[(col + 1) * LDP + row]     = rnaf(fmaxf(acc[mt][nt][1] + bb1, 0.f));
            sH[col * LDP + row + 8]       = rnaf(fmaxf(acc[mt][nt][2] + bb0, 0.f));
            sH[(col + 1) * LDP + row + 8] = rnaf(fmaxf(acc[mt][nt][3] + bb1, 0.f));
            acc[mt][nt][0] = 0.f; acc[mt][nt][1] = 0.f;
            acc[mt][nt][2] = 0.f; acc[mt][nt][3] = 0.f;
        }
    }
    __syncthreads();

    // -------- GEMM2: h[128x128] @ W2 --------
    fetchB(W2, 0);
    for (int c = 0; c < 4; c++) {
        storeB();
        __syncthreads();
        if (c < 3) fetchB(W2, c + 1);
        mmastep(sH + c * 32 * LDP);
        __syncthreads();
    }

    // -------- epilogue 2: out = D2 + b2 --------
    #pragma unroll
    for (int mt = 0; mt < 2; mt++) {
        int row = m0 + 16 * mt + g;
        if (rowBase + row < NCELLS) {
            float* o = out + (size_t)(rowBase + row) * 128;
            #pragma unroll
            for (int nt = 0; nt < 4; nt++) {
                int col = n0 + 8 * nt + 2 * tig;
                float2 v = make_float2(acc[mt][nt][0] + b2s[col],
                                       acc[mt][nt][1] + b2s[col + 1]);
                *(float2*)(o + col) = v;
            }
        }
        if (rowBase + row + 8 < NCELLS) {
            float* o = out + (size_t)(rowBase + row + 8) * 128;
            #pragma unroll
            for (int nt = 0; nt < 4; nt++) {
                int col = n0 + 8 * nt + 2 * tig;
                float2 v = make_float2(acc[mt][nt][2] + b2s[col],
                                       acc[mt][nt][3] + b2s[col + 1]);
                *(float2*)(o + col) = v;
            }
        }
    }
}

// ---------------- scatter cell outputs to node sums + counts ----------------
__global__ void scatter_cell_kernel(const float* __restrict__ cell_out,
                                    const int*   __restrict__ face,
                                    float* __restrict__ node_out) {
    int w    = (blockIdx.x * blockDim.x + threadIdx.x) >> 5;
    int lane = threadIdx.x & 31;
    if (w >= THREEC) return;
    int node = face[w];
    int c = w;
    if (c >= NCELLS) c -= NCELLS;
    if (c >= NCELLS) c -= NCELLS;

    float4 v = __ldg(((const float4*)cell_out) + (size_t)c * 32 + lane);
    float* dst = node_out + (size_t)node * DIM + lane * 4;
    asm volatile("red.global.add.v4.f32 [%0], {%1,%2,%3,%4};"
                 :: "l"(dst), "f"(v.x), "f"(v.y), "f"(v.z), "f"(v.w)
                 : "memory");
    if (lane == 0) atomicAdd(&g_counts[node], 1.f);
}

__global__ void finalize_kernel(float* __restrict__ node_out) {
    int i = blockIdx.x * 256 + threadIdx.x;
    if (i >= NNODES * DIM / 4) return;
    float inv = 1.f / fmaxf(g_counts[i >> 5], 1.f);
    float4 v = ((float4*)node_out)[i];
    v.x *= inv; v.y *= inv; v.z *= inv; v.w *= inv;
    ((float4*)node_out)[i] = v;
}

// ---------------- launch ----------------
extern "C" void kernel_launch(void* const* d_in, const int* in_sizes, int n_in,
                              void* d_out, int out_size) {
    const float* cell_attr  = (const float*)d_in[0];
    const float* edge_attr  = (const float*)d_in[1];
    const float* node_emb   = (const float*)d_in[2];
    const int*   edge_index = (const int*)d_in[3];
    const int*   face       = (const int*)d_in[4];
    const float* W1 = (const float*)d_in[5];
    const float* b1 = (const float*)d_in[6];
    const float* W2 = (const float*)d_in[7];
    const float* b2 = (const float*)d_in[8];

    float* out      = (float*)d_out;
    float* cell_out = out;
    float* node_out = out + (size_t)NCELLS * DIM;

    cudaFuncSetAttribute(mlp_mma_kernel,
                         cudaFuncAttributeMaxDynamicSharedMemorySize, MLP_SMEM);

    zero_kernel<<<50000, 256>>>(node_out);
    attn_kernel<<<37500, 256>>>(edge_attr, node_emb, edge_index);
    normalize_kernel<<<12500, 256>>>();
    mlp_mma_kernel<<<1563, 512, MLP_SMEM>>>(cell_attr, face, W1, b1, W2, b2, cell_out);
    scatter_cell_kernel<<<75000, 256>>>(cell_out, face, node_out);
    finalize_kernel<<<12500, 256>>>(node_out);
}

// round 7
// speedup vs baseline: 1.7808x; 1.0560x over previous
#include <cuda_runtime.h>
#include <math.h>
#include <cstdint>

#define NNODES 100000
#define NCELLS 200000
#define NEDGES 300000
#define DIM 128
#define THREEC (3*NCELLS)

// ---------------- scratch (static device globals: allocation-free) ----------
__device__ float g_nodesum[NNODES];
__device__ float g_counts[NNODES];
__device__ float g_nodeagg[(size_t)NNODES * DIM];

// ---------------- helpers ----------------
__device__ __forceinline__ uint32_t rna(float x) {
    uint32_t u; asm("cvt.rna.tf32.f32 %0, %1;" : "=r"(u) : "f"(x)); return u;
}
__device__ __forceinline__ float rnaf(float x) { return __uint_as_float(rna(x)); }

__device__ __forceinline__ void mma8(float c[4], const uint32_t a[4], const uint32_t b[2]) {
    asm volatile("mma.sync.aligned.m16n8k8.row.col.f32.tf32.tf32.f32 "
        "{%0,%1,%2,%3}, {%4,%5,%6,%7}, {%8,%9}, {%0,%1,%2,%3};"
        : "+f"(c[0]), "+f"(c[1]), "+f"(c[2]), "+f"(c[3])
        : "r"(a[0]), "r"(a[1]), "r"(a[2]), "r"(a[3]), "r"(b[0]), "r"(b[1]));
}

// ---------------- zero init ----------------
__global__ void zero_kernel(float* __restrict__ node_out) {
    int i = blockIdx.x * 256 + threadIdx.x;
    if (i < NNODES * DIM) { g_nodeagg[i] = 0.f; node_out[i] = 0.f; }
    if (i < NNODES)       { g_nodesum[i] = 0.f; g_counts[i] = 0.f; }
}

// ---------------- fused attention: one warp per EDGE, both directions -------
__global__ void attn_kernel(const float* __restrict__ edge_attr,
                            const float* __restrict__ node_emb,
                            const int*   __restrict__ edge_index) {
    int e    = (blockIdx.x * blockDim.x + threadIdx.x) >> 5;
    int lane = threadIdx.x & 31;
    if (e >= NEDGES) return;
    int s = __ldg(edge_index + e);
    int r = __ldg(edge_index + NEDGES + e);

    float4 a  = __ldg(((const float4*)edge_attr) + (size_t)e * 32 + lane);
    float4 bs = __ldg(((const float4*)node_emb)  + (size_t)s * 32 + lane);
    float4 br = __ldg(((const float4*)node_emb)  + (size_t)r * 32 + lane);
    float ds = a.x * bs.x + a.y * bs.y + a.z * bs.z + a.w * bs.w;
    float dr = a.x * br.x + a.y * br.y + a.z * br.z + a.w * br.w;
    #pragma unroll
    for (int off = 16; off > 0; off >>= 1) {
        ds += __shfl_xor_sync(0xffffffffu, ds, off);
        dr += __shfl_xor_sync(0xffffffffu, dr, off);
    }
    float es = expf(ds * 0.08838834764831845f);   // logits bounded, no max-shift
    float er = expf(dr * 0.08838834764831845f);

    float* dstr = g_nodeagg + (size_t)r * DIM + lane * 4;
    asm volatile("red.global.add.v4.f32 [%0], {%1,%2,%3,%4};"
                 :: "l"(dstr), "f"(a.x * er), "f"(a.y * er), "f"(a.z * er), "f"(a.w * er)
                 : "memory");
    float* dsts = g_nodeagg + (size_t)s * DIM + lane * 4;
    asm volatile("red.global.add.v4.f32 [%0], {%1,%2,%3,%4};"
                 :: "l"(dsts), "f"(a.x * es), "f"(a.y * es), "f"(a.z * es), "f"(a.w * es)
                 : "memory");
    if (lane == 0) atomicAdd(&g_nodesum[r], er);
    if (lane == 1) atomicAdd(&g_nodesum[s], es);
}

// ============================================================================
// fused MLP on tf32 mma.sync, 512 threads (16 warps, warp tile 32x32), BK=32
// A and h staged m-major (LDA=36/LDH=132): STS.128 stores + conflict-free
// fragment LDS (bank = 4g + tig). B k-major LDB=136 (bank = 8*tig + g).
// Double-buffered sA/sB: ONE __syncthreads per k-chunk.
// Softmax normalization folded into the gather (sInv = inv3 / nodesum).
// ============================================================================
#define LDA 36
#define LDB 136
#define LDH 132
#define A_CH (128*LDA)          // 4608 floats per A buffer
#define B_CH (32*LDB)           // 4352 floats per B buffer
#define SA_OFF 0
#define SB_OFF (2*A_CH)
#define SH_OFF (SB_OFF + 2*B_CH)
#define B1_OFF (SH_OFF + 128*LDH)
#define B2_OFF (B1_OFF + 128)
#define SF_OFF (B2_OFF + 128)
#define SINV_OFF (SF_OFF + 384)
#define SMEM_FLOATS (SINV_OFF + 384)
#define MLP_SMEM (SMEM_FLOATS * 4)

__global__ __launch_bounds__(512, 1)
void mlp_mma_kernel(const float* __restrict__ cell_attr, const int* __restrict__ face,
                    const float* __restrict__ W1, const float* __restrict__ b1,
                    const float* __restrict__ W2, const float* __restrict__ b2,
                    float* __restrict__ out) {
    extern __shared__ float sm[];
    float* sA   = sm + SA_OFF;
    float* sB   = sm + SB_OFF;
    float* sH   = sm + SH_OFF;
    float* b1s  = sm + B1_OFF;
    float* b2s  = sm + B2_OFF;
    int*   sF   = (int*)(sm + SF_OFF);
    float* sInv = sm + SINV_OFF;

    const int tid  = threadIdx.x;
    const int wid  = tid >> 5, lane = tid & 31;
    const int g    = lane >> 2, tig = lane & 3;
    const int m0   = (wid & 3) * 32, n0 = (wid >> 2) * 32;
    const int rowBase = blockIdx.x * 128;
    const float inv3 = 1.f / 3.f;

    if (tid < 128) {
        b1s[tid] = b1[tid]; b2s[tid] = b2[tid];
        int r = rowBase + tid;
        bool ok = r < NCELLS;
        #pragma unroll
        for (int q = 0; q < 3; q++) {
            int f = ok ? face[q * NCELLS + r] : 0;
            sF[q * 128 + tid] = f;
            float s = g_nodesum[f];
            sInv[q * 128 + tid] = (s > 0.f) ? (inv3 / s) : 0.f;
        }
    }
    // sF/sInv first consumed by fetchA(c>=4), which runs after >=3 syncs.

    float acc[2][4][4];
    #pragma unroll
    for (int mt = 0; mt < 2; mt++)
        #pragma unroll
        for (int nt = 0; nt < 4; nt++)
            #pragma unroll
            for (int q = 0; q < 4; q++) acc[mt][nt][q] = 0.f;

    float4 pa[2], pb[2];

    // ---- A chunk (128 rows x 32 k): 1024 float4, 2 per thread ----
    auto fetchA = [&](int c) {
        #pragma unroll
        for (int h = 0; h < 2; h++) {
            int j = tid + h * 512;
            int m = j >> 3, kq = (j & 7) * 4;
            float4 v = make_float4(0.f, 0.f, 0.f, 0.f);
            int r = rowBase + m;
            if (r < NCELLS) {
                if (c < 4) {
                    v = __ldg((const float4*)(cell_attr + (size_t)r * 128 + c * 32 + kq));
                } else {
                    int gk = (c - 4) * 32 + kq;
                    float i0 = sInv[m], i1 = sInv[128 + m], i2 = sInv[256 + m];
                    float4 a0 = __ldg((const float4*)(g_nodeagg + (size_t)sF[m]       * 128 + gk));
                    float4 a1 = __ldg((const float4*)(g_nodeagg + (size_t)sF[128 + m] * 128 + gk));
                    float4 a2 = __ldg((const float4*)(g_nodeagg + (size_t)sF[256 + m] * 128 + gk));
                    v.x = a0.x * i0 + a1.x * i1 + a2.x * i2;
                    v.y = a0.y * i0 + a1.y * i1 + a2.y * i2;
                    v.z = a0.z * i0 + a1.z * i1 + a2.z * i2;
                    v.w = a0.w * i0 + a1.w * i1 + a2.w * i2;
                }
            }
            pa[h] = v;
        }
    };
    auto storeA = [&](int buf) {
        float* dst = sA + buf * A_CH;
        #pragma unroll
        for (int h = 0; h < 2; h++) {
            int j = tid + h * 512;
            int m = j >> 3, kq = (j & 7) * 4;
            float4 v;
            v.x = rnaf(pa[h].x); v.y = rnaf(pa[h].y);
            v.z = rnaf(pa[h].z); v.w = rnaf(pa[h].w);
            *(float4*)(dst + m * LDA + kq) = v;       // m-major: STS.128, no conflicts
        }
    };
    auto fetchB = [&](const float* W, int c) {
        #pragma unroll
        for (int h = 0; h < 2; h++) {
            int j = tid + h * 512;
            int k = j >> 5, n4 = (j & 31) * 4;
            pb[h] = __ldg((const float4*)(W + (size_t)(c * 32 + k) * 128 + n4));
        }
    };
    auto storeB = [&](int buf) {
        float* dst = sB + buf * B_CH;
        #pragma unroll
        for (int h = 0; h < 2; h++) {
            int j = tid + h * 512;
            int k = j >> 5, n4 = (j & 31) * 4;
            float4 v;
            v.x = rnaf(pb[h].x); v.y = rnaf(pb[h].y);
            v.z = rnaf(pb[h].z); v.w = rnaf(pb[h].w);
            *(float4*)(dst + k * LDB + n4) = v;
        }
    };
    auto mmastep = [&](const float* Ab, int lda, const float* Bb) {
        #pragma unroll
        for (int k0 = 0; k0 < 32; k0 += 8) {
            uint32_t af[2][4], bf[4][2];
            #pragma unroll
            for (int mt = 0; mt < 2; mt++) {
                const float* ar = Ab + (m0 + 16 * mt + g) * lda + k0;
                af[mt][0] = __float_as_uint(ar[tig]);
                af[mt][1] = __float_as_uint(ar[8 * lda + tig]);
                af[mt][2] = __float_as_uint(ar[tig + 4]);
                af[mt][3] = __float_as_uint(ar[8 * lda + tig + 4]);
            }
            const float* br = Bb + k0 * LDB;
            #pragma unroll
            for (int nt = 0; nt < 4; nt++) {
                int nn = n0 + 8 * nt + g;
                bf[nt][0] = __float_as_uint(br[tig * LDB + nn]);
                bf[nt][1] = __float_as_uint(br[(tig + 4) * LDB + nn]);
            }
            #pragma unroll
            for (int mt = 0; mt < 2; mt++)
                #pragma unroll
                for (int nt = 0; nt < 4; nt++)
                    mma8(acc[mt][nt], af[mt], bf[nt]);
        }
    };

    // -------- GEMM1: concat(cell_attr, cell_agg)[128x256] @ W1 --------
    fetchA(0); fetchB(W1, 0);
    storeA(0); storeB(0);
    __syncthreads();
    for (int c = 0; c < 8; c++) {
        int buf = c & 1;
        if (c < 7) { fetchA(c + 1); fetchB(W1, c + 1); }
        mmastep(sA + buf * A_CH, LDA, sB + buf * B_CH);
        if (c < 7) {
            storeA(buf ^ 1); storeB(buf ^ 1);
            __syncthreads();
        }
    }

    // -------- epilogue 1: h = relu(D1 + b1) -> sH m-major, tf32-rounded --------
    #pragma unroll
    for (int mt = 0; mt < 2; mt++) {
        int row = m0 + 16 * mt + g;
        #pragma unroll
        for (int nt = 0; nt < 4; nt++) {
            int col = n0 + 8 * nt + 2 * tig;
            float bb0 = b1s[col], bb1 = b1s[col + 1];
            float2 h0, h1;
            h0.x = rnaf(fmaxf(acc[mt][nt][0] + bb0, 0.f));
            h0.y = rnaf(fmaxf(acc[mt][nt][1] + bb1, 0.f));
            h1.x = rnaf(fmaxf(acc[mt][nt][2] + bb0, 0.f));
            h1.y = rnaf(fmaxf(acc[mt][nt][3] + bb1, 0.f));
            *(float2*)(sH + row * LDH + col)       = h0;
            *(float2*)(sH + (row + 8) * LDH + col) = h1;
            acc[mt][nt][0] = 0.f; acc[mt][nt][1] = 0.f;
            acc[mt][nt][2] = 0.f; acc[mt][nt][3] = 0.f;
        }
    }
    // prefetch first W2 chunk into buf0 (buf0 free: last read before prior sync)
    fetchB(W2, 0);
    storeB(0);
    __syncthreads();   // covers sH writes + W2 buf0

    // -------- GEMM2: h[128x128] @ W2 --------
    for (int c = 0; c < 4; c++) {
        int buf = c & 1;
        if (c < 3) fetchB(W2, c + 1);
        mmastep(sH + c * 32, LDH, sB + buf * B_CH);
        if (c < 3) {
            storeB(buf ^ 1);
            __syncthreads();
        }
    }

    // -------- epilogue 2: out = D2 + b2 --------
    #pragma unroll
    for (int mt = 0; mt < 2; mt++) {
        int row = m0 + 16 * mt + g;
        if (rowBase + row < NCELLS) {
            float* o = out + (size_t)(rowBase + row) * 128;
            #pragma unroll
            for (int nt = 0; nt < 4; nt++) {
                int col = n0 + 8 * nt + 2 * tig;
                float2 v = make_float2(acc[mt][nt][0] + b2s[col],
                                       acc[mt][nt][1] + b2s[col + 1]);
                *(float2*)(o + col) = v;
            }
        }
        if (rowBase + row + 8 < NCELLS) {
            float* o = out + (size_t)(rowBase + row + 8) * 128;
            #pragma unroll
            for (int nt = 0; nt < 4; nt++) {
                int col = n0 + 8 * nt + 2 * tig;
                float2 v = make_float2(acc[mt][nt][2] + b2s[col],
                                       acc[mt][nt][3] + b2s[col + 1]);
                *(float2*)(o + col) = v;
            }
        }
    }
}

// ---------------- scatter cell outputs to node sums + counts ----------------
__global__ void scatter_cell_kernel(const float* __restrict__ cell_out,
                                    const int*   __restrict__ face,
                                    float* __restrict__ node_out) {
    int w    = (blockIdx.x * blockDim.x + threadIdx.x) >> 5;
    int lane = threadIdx.x & 31;
    if (w >= THREEC) return;
    int node = face[w];
    int c = w;
    if (c >= NCELLS) c -= NCELLS;
    if (c >= NCELLS) c -= NCELLS;

    float4 v = __ldg(((const float4*)cell_out) + (size_t)c * 32 + lane);
    float* dst = node_out + (size_t)node * DIM + lane * 4;
    asm volatile("red.global.add.v4.f32 [%0], {%1,%2,%3,%4};"
                 :: "l"(dst), "f"(v.x), "f"(v.y), "f"(v.z), "f"(v.w)
                 : "memory");
    if (lane == 0) atomicAdd(&g_counts[node], 1.f);
}

__global__ void finalize_kernel(float* __restrict__ node_out) {
    int i = blockIdx.x * 256 + threadIdx.x;
    if (i >= NNODES * DIM / 4) return;
    float inv = 1.f / fmaxf(g_counts[i >> 5], 1.f);
    float4 v = ((float4*)node_out)[i];
    v.x *= inv; v.y *= inv; v.z *= inv; v.w *= inv;
    ((float4*)node_out)[i] = v;
}

// ---------------- launch ----------------
extern "C" void kernel_launch(void* const* d_in, const int* in_sizes, int n_in,
                              void* d_out, int out_size) {
    const float* cell_attr  = (const float*)d_in[0];
    const float* edge_attr  = (const float*)d_in[1];
    const float* node_emb   = (const float*)d_in[2];
    const int*   edge_index = (const int*)d_in[3];
    const int*   face       = (const int*)d_in[4];
    const float* W1 = (const float*)d_in[5];
    const float* b1 = (const float*)d_in[6];
    const float* W2 = (const float*)d_in[7];
    const float* b2 = (const float*)d_in[8];

    float* out      = (float*)d_out;
    float* cell_out = out;
    float* node_out = out + (size_t)NCELLS * DIM;

    cudaFuncSetAttribute(mlp_mma_kernel,
                         cudaFuncAttributeMaxDynamicSharedMemorySize, MLP_SMEM);

    zero_kernel<<<50000, 256>>>(node_out);
    attn_kernel<<<37500, 256>>>(edge_attr, node_emb, edge_index);
    mlp_mma_kernel<<<1563, 512, MLP_SMEM>>>(cell_attr, face, W1, b1, W2, b2, cell_out);
    scatter_cell_kernel<<<75000, 256>>>(cell_out, face, node_out);
    finalize_kernel<<<12500, 256>>>(node_out);
}

// round 8
// speedup vs baseline: 1.8888x; 1.0607x over previous
#include <cuda_runtime.h>
#include <math.h>
#include <cstdint>

#define NNODES 100000
#define NCELLS 200000
#define NEDGES 300000
#define DIM 128
#define THREEC (3*NCELLS)

// ---------------- scratch (static device globals: allocation-free) ----------
__device__ float g_nodesum[NNODES];
__device__ float g_counts[NNODES];
__device__ float g_nodeagg[(size_t)NNODES * DIM];

// ---------------- helpers ----------------
__device__ __forceinline__ uint32_t rna(float x) {
    uint32_t u; asm("cvt.rna.tf32.f32 %0, %1;" : "=r"(u) : "f"(x)); return u;
}
__device__ __forceinline__ float rnaf(float x) { return __uint_as_float(rna(x)); }

__device__ __forceinline__ void mma8(float c[4], const uint32_t a[4], const uint32_t b[2]) {
    asm volatile("mma.sync.aligned.m16n8k8.row.col.f32.tf32.tf32.f32 "
        "{%0,%1,%2,%3}, {%4,%5,%6,%7}, {%8,%9}, {%0,%1,%2,%3};"
        : "+f"(c[0]), "+f"(c[1]), "+f"(c[2]), "+f"(c[3])
        : "r"(a[0]), "r"(a[1]), "r"(a[2]), "r"(a[3]), "r"(b[0]), "r"(b[1]));
}

// ---------------- zero init ----------------
__global__ void zero_kernel(float* __restrict__ node_out) {
    int i = blockIdx.x * 256 + threadIdx.x;
    if (i < NNODES * DIM) { g_nodeagg[i] = 0.f; node_out[i] = 0.f; }
    if (i < NNODES)       { g_nodesum[i] = 0.f; g_counts[i] = 0.f; }
}

// ---------------- fused attention: one warp per EDGE, both directions -------
__global__ void attn_kernel(const float* __restrict__ edge_attr,
                            const float* __restrict__ node_emb,
                            const int*   __restrict__ edge_index) {
    int e    = (blockIdx.x * blockDim.x + threadIdx.x) >> 5;
    int lane = threadIdx.x & 31;
    if (e >= NEDGES) return;
    int s = __ldg(edge_index + e);
    int r = __ldg(edge_index + NEDGES + e);

    float4 a  = __ldg(((const float4*)edge_attr) + (size_t)e * 32 + lane);
    float4 bs = __ldg(((const float4*)node_emb)  + (size_t)s * 32 + lane);
    float4 br = __ldg(((const float4*)node_emb)  + (size_t)r * 32 + lane);
    float ds = a.x * bs.x + a.y * bs.y + a.z * bs.z + a.w * bs.w;
    float dr = a.x * br.x + a.y * br.y + a.z * br.z + a.w * br.w;
    #pragma unroll
    for (int off = 16; off > 0; off >>= 1) {
        ds += __shfl_xor_sync(0xffffffffu, ds, off);
        dr += __shfl_xor_sync(0xffffffffu, dr, off);
    }
    float es = expf(ds * 0.08838834764831845f);   // logits bounded, no max-shift
    float er = expf(dr * 0.08838834764831845f);

    float* dstr = g_nodeagg + (size_t)r * DIM + lane * 4;
    asm volatile("red.global.add.v4.f32 [%0], {%1,%2,%3,%4};"
                 :: "l"(dstr), "f"(a.x * er), "f"(a.y * er), "f"(a.z * er), "f"(a.w * er)
                 : "memory");
    float* dsts = g_nodeagg + (size_t)s * DIM + lane * 4;
    asm volatile("red.global.add.v4.f32 [%0], {%1,%2,%3,%4};"
                 :: "l"(dsts), "f"(a.x * es), "f"(a.y * es), "f"(a.z * es), "f"(a.w * es)
                 : "memory");
    if (lane == 0) atomicAdd(&g_nodesum[r], er);
    if (lane == 1) atomicAdd(&g_nodesum[s], es);
}

// ============================================================================
// fused MLP on tf32 mma.sync
// M-tile=64 (grid 3125 = 200000/64, no bounds checks), 256 threads, 8 warps
// (2 m-warps x 4 n-warps, warp tile 32x32), BK=32, double-buffered A/B.
// h[64x132] overlaps the A double-buffer region (union) -> 71KB SMEM/CTA,
// 2 CTAs/SM for cross-CTA latency hiding.
// ============================================================================
#define LDA 36
#define LDB 136
#define LDH 132
#define MTILE 64
#define A_CH (MTILE*LDA)            // 2304 floats per A buffer
#define B_CH (32*LDB)               // 4352 floats per B buffer
#define UNION_FLOATS (MTILE*LDH)    // 8448 >= 2*A_CH (4608)
#define SB_OFF UNION_FLOATS
#define B1_OFF (SB_OFF + 2*B_CH)
#define B2_OFF (B1_OFF + 128)
#define SF_OFF (B2_OFF + 128)
#define SINV_OFF (SF_OFF + 3*MTILE)
#define SMEM_FLOATS (SINV_OFF + 3*MTILE)
#define MLP_SMEM (SMEM_FLOATS * 4)

__global__ __launch_bounds__(256, 2)
void mlp_mma_kernel(const float* __restrict__ cell_attr, const int* __restrict__ face,
                    const float* __restrict__ W1, const float* __restrict__ b1,
                    const float* __restrict__ W2, const float* __restrict__ b2,
                    float* __restrict__ out) {
    extern __shared__ float sm[];
    float* sA   = sm;                 // 2 x A_CH (within union)
    float* sH   = sm;                 // 64 x LDH (union, after GEMM1)
    float* sB   = sm + SB_OFF;
    float* b1s  = sm + B1_OFF;
    float* b2s  = sm + B2_OFF;
    int*   sF   = (int*)(sm + SF_OFF);
    float* sInv = sm + SINV_OFF;

    const int tid  = threadIdx.x;
    const int wid  = tid >> 5, lane = tid & 31;
    const int g    = lane >> 2, tig = lane & 3;
    const int m0   = (wid & 1) * 32, n0 = (wid >> 1) * 32;
    const int rowBase = blockIdx.x * MTILE;
    const float inv3 = 1.f / 3.f;

    if (tid < 128) { b1s[tid] = b1[tid]; b2s[tid] = b2[tid]; }
    if (tid < MTILE) {
        int r = rowBase + tid;
        #pragma unroll
        for (int q = 0; q < 3; q++) {
            int f = face[q * NCELLS + r];
            sF[q * MTILE + tid] = f;
            float s = g_nodesum[f];
            sInv[q * MTILE + tid] = (s > 0.f) ? (inv3 / s) : 0.f;
        }
    }
    // sF/sInv first consumed by fetchA(c>=4), after several syncs.

    float acc[2][4][4];
    #pragma unroll
    for (int mt = 0; mt < 2; mt++)
        #pragma unroll
        for (int nt = 0; nt < 4; nt++)
            #pragma unroll
            for (int q = 0; q < 4; q++) acc[mt][nt][q] = 0.f;

    float4 pa[2], pb[4];

    // ---- A chunk (64 rows x 32 k): 512 float4, 2 per thread ----
    auto fetchA = [&](int c) {
        #pragma unroll
        for (int h = 0; h < 2; h++) {
            int j = tid + h * 256;               // [0,512)
            int m = j >> 3, kq = (j & 7) * 4;
            float4 v;
            int r = rowBase + m;
            if (c < 4) {
                v = __ldg((const float4*)(cell_attr + (size_t)r * 128 + c * 32 + kq));
            } else {
                int gk = (c - 4) * 32 + kq;
                float i0 = sInv[m], i1 = sInv[MTILE + m], i2 = sInv[2 * MTILE + m];
                float4 a0 = __ldg((const float4*)(g_nodeagg + (size_t)sF[m]           * 128 + gk));
                float4 a1 = __ldg((const float4*)(g_nodeagg + (size_t)sF[MTILE + m]   * 128 + gk));
                float4 a2 = __ldg((const float4*)(g_nodeagg + (size_t)sF[2*MTILE + m] * 128 + gk));
                v.x = a0.x * i0 + a1.x * i1 + a2.x * i2;
                v.y = a0.y * i0 + a1.y * i1 + a2.y * i2;
                v.z = a0.z * i0 + a1.z * i1 + a2.z * i2;
                v.w = a0.w * i0 + a1.w * i1 + a2.w * i2;
            }
            pa[h] = v;
        }
    };
    auto storeA = [&](int buf) {
        float* dst = sA + buf * A_CH;
        #pragma unroll
        for (int h = 0; h < 2; h++) {
            int j = tid + h * 256;
            int m = j >> 3, kq = (j & 7) * 4;
            float4 v;
            v.x = rnaf(pa[h].x); v.y = rnaf(pa[h].y);
            v.z = rnaf(pa[h].z); v.w = rnaf(pa[h].w);
            *(float4*)(dst + m * LDA + kq) = v;   // m-major STS.128, conflict-free
        }
    };
    // ---- B chunk (32 k x 128 n): 1024 float4, 4 per thread ----
    auto fetchB = [&](const float* W, int c) {
        #pragma unroll
        for (int h = 0; h < 4; h++) {
            int j = tid + h * 256;
            int k = j >> 5, n4 = (j & 31) * 4;
            pb[h] = __ldg((const float4*)(W + (size_t)(c * 32 + k) * 128 + n4));
        }
    };
    auto storeB = [&](int buf) {
        float* dst = sB + buf * B_CH;
        #pragma unroll
        for (int h = 0; h < 4; h++) {
            int j = tid + h * 256;
            int k = j >> 5, n4 = (j & 31) * 4;
            float4 v;
            v.x = rnaf(pb[h].x); v.y = rnaf(pb[h].y);
            v.z = rnaf(pb[h].z); v.w = rnaf(pb[h].w);
            *(float4*)(dst + k * LDB + n4) = v;
        }
    };
    auto mmastep = [&](const float* Ab, int lda, const float* Bb) {
        #pragma unroll
        for (int k0 = 0; k0 < 32; k0 += 8) {
            uint32_t af[2][4], bf[4][2];
            #pragma unroll
            for (int mt = 0; mt < 2; mt++) {
                const float* ar = Ab + (m0 + 16 * mt + g) * lda + k0;
                af[mt][0] = __float_as_uint(ar[tig]);
                af[mt][1] = __float_as_uint(ar[8 * lda + tig]);
                af[mt][2] = __float_as_uint(ar[tig + 4]);
                af[mt][3] = __float_as_uint(ar[8 * lda + tig + 4]);
            }
            const float* br = Bb + k0 * LDB;
            #pragma unroll
            for (int nt = 0; nt < 4; nt++) {
                int nn = n0 + 8 * nt + g;
                bf[nt][0] = __float_as_uint(br[tig * LDB + nn]);
                bf[nt][1] = __float_as_uint(br[(tig + 4) * LDB + nn]);
            }
            #pragma unroll
            for (int mt = 0; mt < 2; mt++)
                #pragma unroll
                for (int nt = 0; nt < 4; nt++)
                    mma8(acc[mt][nt], af[mt], bf[nt]);
        }
    };

    // -------- GEMM1: concat(cell_attr, cell_agg)[64x256] @ W1 --------
    fetchA(0); fetchB(W1, 0);
    storeA(0); storeB(0);
    __syncthreads();
    for (int c = 0; c < 8; c++) {
        int buf = c & 1;
        if (c < 7) { fetchA(c + 1); fetchB(W1, c + 1); }
        mmastep(sA + buf * A_CH, LDA, sB + buf * B_CH);
        if (c < 7) {
            storeA(buf ^ 1); storeB(buf ^ 1);
            __syncthreads();
        }
    }
    __syncthreads();   // all warps done reading A bufs before h overwrites union

    // -------- epilogue 1: h = relu(D1 + b1) -> sH (union), tf32-rounded --------
    #pragma unroll
    for (int mt = 0; mt < 2; mt++) {
        int row = m0 + 16 * mt + g;
        #pragma unroll
        for (int nt = 0; nt < 4; nt++) {
            int col = n0 + 8 * nt + 2 * tig;
            float bb0 = b1s[col], bb1 = b1s[col + 1];
            float2 h0, h1;
            h0.x = rnaf(fmaxf(acc[mt][nt][0] + bb0, 0.f));
            h0.y = rnaf(fmaxf(acc[mt][nt][1] + bb1, 0.f));
            h1.x = rnaf(fmaxf(acc[mt][nt][2] + bb0, 0.f));
            h1.y = rnaf(fmaxf(acc[mt][nt][3] + bb1, 0.f));
            *(float2*)(sH + row * LDH + col)       = h0;
            *(float2*)(sH + (row + 8) * LDH + col) = h1;
            acc[mt][nt][0] = 0.f; acc[mt][nt][1] = 0.f;
            acc[mt][nt][2] = 0.f; acc[mt][nt][3] = 0.f;
        }
    }
    fetchB(W2, 0);
    storeB(0);
    __syncthreads();   // covers sH writes + W2 buf0

    // -------- GEMM2: h[64x128] @ W2 --------
    for (int c = 0; c < 4; c++) {
        int buf = c & 1;
        if (c < 3) fetchB(W2, c + 1);
        mmastep(sH + c * 32, LDH, sB + buf * B_CH);
        if (c < 3) {
            storeB(buf ^ 1);
            __syncthreads();
        }
    }

    // -------- epilogue 2: out = D2 + b2 --------
    #pragma unroll
    for (int mt = 0; mt < 2; mt++) {
        int row = m0 + 16 * mt + g;
        float* o0 = out + (size_t)(rowBase + row) * 128;
        float* o1 = out + (size_t)(rowBase + row + 8) * 128;
        #pragma unroll
        for (int nt = 0; nt < 4; nt++) {
            int col = n0 + 8 * nt + 2 * tig;
            *(float2*)(o0 + col) = make_float2(acc[mt][nt][0] + b2s[col],
                                               acc[mt][nt][1] + b2s[col + 1]);
            *(float2*)(o1 + col) = make_float2(acc[mt][nt][2] + b2s[col],
                                               acc[mt][nt][3] + b2s[col + 1]);
        }
    }
}

// ---------------- scatter cell outputs to node sums + counts ----------------
__global__ void scatter_cell_kernel(const float* __restrict__ cell_out,
                                    const int*   __restrict__ face,
                                    float* __restrict__ node_out) {
    int w    = (blockIdx.x * blockDim.x + threadIdx.x) >> 5;
    int lane = threadIdx.x & 31;
    if (w >= THREEC) return;
    int node = face[w];
    int c = w;
    if (c >= NCELLS) c -= NCELLS;
    if (c >= NCELLS) c -= NCELLS;

    float4 v = __ldg(((const float4*)cell_out) + (size_t)c * 32 + lane);
    float* dst = node_out + (size_t)node * DIM + lane * 4;
    asm volatile("red.global.add.v4.f32 [%0], {%1,%2,%3,%4};"
                 :: "l"(dst), "f"(v.x), "f"(v.y), "f"(v.z), "f"(v.w)
                 : "memory");
    if (lane == 0) atomicAdd(&g_counts[node], 1.f);
}

__global__ void finalize_kernel(float* __restrict__ node_out) {
    int i = blockIdx.x * 256 + threadIdx.x;
    if (i >= NNODES * DIM / 4) return;
    float inv = 1.f / fmaxf(g_counts[i >> 5], 1.f);
    float4 v = ((float4*)node_out)[i];
    v.x *= inv; v.y *= inv; v.z *= inv; v.w *= inv;
    ((float4*)node_out)[i] = v;
}

// ---------------- launch ----------------
extern "C" void kernel_launch(void* const* d_in, const int* in_sizes, int n_in,
                              void* d_out, int out_size) {
    const float* cell_attr  = (const float*)d_in[0];
    const float* edge_attr  = (const float*)d_in[1];
    const float* node_emb   = (const float*)d_in[2];
    const int*   edge_index = (const int*)d_in[3];
    const int*   face       = (const int*)d_in[4];
    const float* W1 = (const float*)d_in[5];
    const float* b1 = (const float*)d_in[6];
    const float* W2 = (const float*)d_in[7];
    const float* b2 = (const float*)d_in[8];

    float* out      = (float*)d_out;
    float* cell_out = out;
    float* node_out = out + (size_t)NCELLS * DIM;

    cudaFuncSetAttribute(mlp_mma_kernel,
                         cudaFuncAttributeMaxDynamicSharedMemorySize, MLP_SMEM);

    zero_kernel<<<50000, 256>>>(node_out);
    attn_kernel<<<37500, 256>>>(edge_attr, node_emb, edge_index);
    mlp_mma_kernel<<<3125, 256, MLP_SMEM>>>(cell_attr, face, W1, b1, W2, b2, cell_out);
    scatter_cell_kernel<<<75000, 256>>>(cell_out, face, node_out);
    finalize_kernel<<<12500, 256>>>(node_out);
}

// round 9
// speedup vs baseline: 1.8933x; 1.0024x over previous
#include <cuda_runtime.h>
#include <math.h>
#include <cstdint>

#define NNODES 100000
#define NCELLS 200000
#define NEDGES 300000
#define DIM 128
#define THREEC (3*NCELLS)

// ---------------- scratch (static device globals: allocation-free) ----------
__device__ float g_nodesum[NNODES];
__device__ float g_counts[NNODES];
__device__ float g_nodeagg[(size_t)NNODES * DIM];

// ---------------- helpers ----------------
__device__ __forceinline__ uint32_t rna(float x) {
    uint32_t u; asm("cvt.rna.tf32.f32 %0, %1;" : "=r"(u) : "f"(x)); return u;
}
__device__ __forceinline__ float rnaf(float x) { return __uint_as_float(rna(x)); }

__device__ __forceinline__ void mma8(float c[4], const uint32_t a[4], const uint32_t b[2]) {
    asm volatile("mma.sync.aligned.m16n8k8.row.col.f32.tf32.tf32.f32 "
        "{%0,%1,%2,%3}, {%4,%5,%6,%7}, {%8,%9}, {%0,%1,%2,%3};"
        : "+f"(c[0]), "+f"(c[1]), "+f"(c[2]), "+f"(c[3])
        : "r"(a[0]), "r"(a[1]), "r"(a[2]), "r"(a[3]), "r"(b[0]), "r"(b[1]));
}

// ---------------- zero init ----------------
__global__ void zero_kernel(float* __restrict__ node_out) {
    int i = blockIdx.x * 256 + threadIdx.x;
    if (i < NNODES * DIM) { g_nodeagg[i] = 0.f; node_out[i] = 0.f; }
    if (i < NNODES)       { g_nodesum[i] = 0.f; g_counts[i] = 0.f; }
}

// ---------------- fused attention: one warp per EDGE, both directions -------
__global__ void attn_kernel(const float* __restrict__ edge_attr,
                            const float* __restrict__ node_emb,
                            const int*   __restrict__ edge_index) {
    int e    = (blockIdx.x * blockDim.x + threadIdx.x) >> 5;
    int lane = threadIdx.x & 31;
    if (e >= NEDGES) return;
    int s = __ldg(edge_index + e);
    int r = __ldg(edge_index + NEDGES + e);

    float4 a  = __ldg(((const float4*)edge_attr) + (size_t)e * 32 + lane);
    float4 bs = __ldg(((const float4*)node_emb)  + (size_t)s * 32 + lane);
    float4 br = __ldg(((const float4*)node_emb)  + (size_t)r * 32 + lane);
    float ds = a.x * bs.x + a.y * bs.y + a.z * bs.z + a.w * bs.w;
    float dr = a.x * br.x + a.y * br.y + a.z * br.z + a.w * br.w;
    #pragma unroll
    for (int off = 16; off > 0; off >>= 1) {
        ds += __shfl_xor_sync(0xffffffffu, ds, off);
        dr += __shfl_xor_sync(0xffffffffu, dr, off);
    }
    float es = expf(ds * 0.08838834764831845f);   // logits bounded, no max-shift
    float er = expf(dr * 0.08838834764831845f);

    float* dstr = g_nodeagg + (size_t)r * DIM + lane * 4;
    asm volatile("red.global.add.v4.f32 [%0], {%1,%2,%3,%4};"
                 :: "l"(dstr), "f"(a.x * er), "f"(a.y * er), "f"(a.z * er), "f"(a.w * er)
                 : "memory");
    float* dsts = g_nodeagg + (size_t)s * DIM + lane * 4;
    asm volatile("red.global.add.v4.f32 [%0], {%1,%2,%3,%4};"
                 :: "l"(dsts), "f"(a.x * es), "f"(a.y * es), "f"(a.z * es), "f"(a.w * es)
                 : "memory");
    if (lane == 0) atomicAdd(&g_nodesum[r], er);
    if (lane == 1) atomicAdd(&g_nodesum[s], es);
}

// ============================================================================
// fused MLP on tf32 mma.sync
// M-tile=64 (grid 3125 = 200000/64, no bounds checks), 256 threads, 8 warps
// (2 m-warps x 4 n-warps, warp tile 32x32), BK=32, double-buffered A/B.
// h[64x132] overlaps the A double-buffer region (union) -> 71KB SMEM/CTA,
// 2 CTAs/SM for cross-CTA latency hiding.
// ============================================================================
#define LDA 36
#define LDB 136
#define LDH 132
#define MTILE 64
#define A_CH (MTILE*LDA)            // 2304 floats per A buffer
#define B_CH (32*LDB)               // 4352 floats per B buffer
#define UNION_FLOATS (MTILE*LDH)    // 8448 >= 2*A_CH (4608)
#define SB_OFF UNION_FLOATS
#define B1_OFF (SB_OFF + 2*B_CH)
#define B2_OFF (B1_OFF + 128)
#define SF_OFF (B2_OFF + 128)
#define SINV_OFF (SF_OFF + 3*MTILE)
#define SMEM_FLOATS (SINV_OFF + 3*MTILE)
#define MLP_SMEM (SMEM_FLOATS * 4)

__global__ __launch_bounds__(256, 2)
void mlp_mma_kernel(const float* __restrict__ cell_attr, const int* __restrict__ face,
                    const float* __restrict__ W1, const float* __restrict__ b1,
                    const float* __restrict__ W2, const float* __restrict__ b2,
                    float* __restrict__ out) {
    extern __shared__ float sm[];
    float* sA   = sm;                 // 2 x A_CH (within union)
    float* sH   = sm;                 // 64 x LDH (union, after GEMM1)
    float* sB   = sm + SB_OFF;
    float* b1s  = sm + B1_OFF;
    float* b2s  = sm + B2_OFF;
    int*   sF   = (int*)(sm + SF_OFF);
    float* sInv = sm + SINV_OFF;

    const int tid  = threadIdx.x;
    const int wid  = tid >> 5, lane = tid & 31;
    const int g    = lane >> 2, tig = lane & 3;
    const int m0   = (wid & 1) * 32, n0 = (wid >> 1) * 32;
    const int rowBase = blockIdx.x * MTILE;
    const float inv3 = 1.f / 3.f;

    if (tid < 128) { b1s[tid] = b1[tid]; b2s[tid] = b2[tid]; }
    if (tid < MTILE) {
        int r = rowBase + tid;
        #pragma unroll
        for (int q = 0; q < 3; q++) {
            int f = face[q * NCELLS + r];
            sF[q * MTILE + tid] = f;
            float s = g_nodesum[f];
            sInv[q * MTILE + tid] = (s > 0.f) ? (inv3 / s) : 0.f;
        }
    }
    // sF/sInv first consumed by fetchA(c>=4), after several syncs.

    float acc[2][4][4];
    #pragma unroll
    for (int mt = 0; mt < 2; mt++)
        #pragma unroll
        for (int nt = 0; nt < 4; nt++)
            #pragma unroll
            for (int q = 0; q < 4; q++) acc[mt][nt][q] = 0.f;

    float4 pa[2], pb[4];

    // ---- A chunk (64 rows x 32 k): 512 float4, 2 per thread ----
    auto fetchA = [&](int c) {
        #pragma unroll
        for (int h = 0; h < 2; h++) {
            int j = tid + h * 256;               // [0,512)
            int m = j >> 3, kq = (j & 7) * 4;
            float4 v;
            int r = rowBase + m;
            if (c < 4) {
                v = __ldg((const float4*)(cell_attr + (size_t)r * 128 + c * 32 + kq));
            } else {
                int gk = (c - 4) * 32 + kq;
                float i0 = sInv[m], i1 = sInv[MTILE + m], i2 = sInv[2 * MTILE + m];
                float4 a0 = __ldg((const float4*)(g_nodeagg + (size_t)sF[m]           * 128 + gk));
                float4 a1 = __ldg((const float4*)(g_nodeagg + (size_t)sF[MTILE + m]   * 128 + gk));
                float4 a2 = __ldg((const float4*)(g_nodeagg + (size_t)sF[2*MTILE + m] * 128 + gk));
                v.x = a0.x * i0 + a1.x * i1 + a2.x * i2;
                v.y = a0.y * i0 + a1.y * i1 + a2.y * i2;
                v.z = a0.z * i0 + a1.z * i1 + a2.z * i2;
                v.w = a0.w * i0 + a1.w * i1 + a2.w * i2;
            }
            pa[h] = v;
        }
    };
    auto storeA = [&](int buf) {
        float* dst = sA + buf * A_CH;
        #pragma unroll
        for (int h = 0; h < 2; h++) {
            int j = tid + h * 256;
            int m = j >> 3, kq = (j & 7) * 4;
            float4 v;
            v.x = rnaf(pa[h].x); v.y = rnaf(pa[h].y);
            v.z = rnaf(pa[h].z); v.w = rnaf(pa[h].w);
            *(float4*)(dst + m * LDA + kq) = v;   // m-major STS.128, conflict-free
        }
    };
    // ---- B chunk (32 k x 128 n): 1024 float4, 4 per thread ----
    auto fetchB = [&](const float* W, int c) {
        #pragma unroll
        for (int h = 0; h < 4; h++) {
            int j = tid + h * 256;
            int k = j >> 5, n4 = (j & 31) * 4;
            pb[h] = __ldg((const float4*)(W + (size_t)(c * 32 + k) * 128 + n4));
        }
    };
    auto storeB = [&](int buf) {
        float* dst = sB + buf * B_CH;
        #pragma unroll
        for (int h = 0; h < 4; h++) {
            int j = tid + h * 256;
            int k = j >> 5, n4 = (j & 31) * 4;
            float4 v;
            v.x = rnaf(pb[h].x); v.y = rnaf(pb[h].y);
            v.z = rnaf(pb[h].z); v.w = rnaf(pb[h].w);
            *(float4*)(dst + k * LDB + n4) = v;
        }
    };
    auto mmastep = [&](const float* Ab, int lda, const float* Bb) {
        #pragma unroll
        for (int k0 = 0; k0 < 32; k0 += 8) {
            uint32_t af[2][4], bf[4][2];
            #pragma unroll
            for (int mt = 0; mt < 2; mt++) {
                const float* ar = Ab + (m0 + 16 * mt + g) * lda + k0;
                af[mt][0] = __float_as_uint(ar[tig]);
                af[mt][1] = __float_as_uint(ar[8 * lda + tig]);
                af[mt][2] = __float_as_uint(ar[tig + 4]);
                af[mt][3] = __float_as_uint(ar[8 * lda + tig + 4]);
            }
            const float* br = Bb + k0 * LDB;
            #pragma unroll
            for (int nt = 0; nt < 4; nt++) {
                int nn = n0 + 8 * nt + g;
                bf[nt][0] = __float_as_uint(br[tig * LDB + nn]);
                bf[nt][1] = __float_as_uint(br[(tig + 4) * LDB + nn]);
            }
            #pragma unroll
            for (int mt = 0; mt < 2; mt++)
                #pragma unroll
                for (int nt = 0; nt < 4; nt++)
                    mma8(acc[mt][nt], af[mt], bf[nt]);
        }
    };

    // -------- GEMM1: concat(cell_attr, cell_agg)[64x256] @ W1 --------
    fetchA(0); fetchB(W1, 0);
    storeA(0); storeB(0);
    __syncthreads();
    for (int c = 0; c < 8; c++) {
        int buf = c & 1;
        if (c < 7) { fetchA(c + 1); fetchB(W1, c + 1); }
        mmastep(sA + buf * A_CH, LDA, sB + buf * B_CH);
        if (c < 7) {
            storeA(buf ^ 1); storeB(buf ^ 1);
            __syncthreads();
        }
    }
    __syncthreads();   // all warps done reading A bufs before h overwrites union

    // -------- epilogue 1: h = relu(D1 + b1) -> sH (union), tf32-rounded --------
    #pragma unroll
    for (int mt = 0; mt < 2; mt++) {
        int row = m0 + 16 * mt + g;
        #pragma unroll
        for (int nt = 0; nt < 4; nt++) {
            int col = n0 + 8 * nt + 2 * tig;
            float bb0 = b1s[col], bb1 = b1s[col + 1];
            float2 h0, h1;
            h0.x = rnaf(fmaxf(acc[mt][nt][0] + bb0, 0.f));
            h0.y = rnaf(fmaxf(acc[mt][nt][1] + bb1, 0.f));
            h1.x = rnaf(fmaxf(acc[mt][nt][2] + bb0, 0.f));
            h1.y = rnaf(fmaxf(acc[mt][nt][3] + bb1, 0.f));
            *(float2*)(sH + row * LDH + col)       = h0;
            *(float2*)(sH + (row + 8) * LDH + col) = h1;
            acc[mt][nt][0] = 0.f; acc[mt][nt][1] = 0.f;
            acc[mt][nt][2] = 0.f; acc[mt][nt][3] = 0.f;
        }
    }
    fetchB(W2, 0);
    storeB(0);
    __syncthreads();   // covers sH writes + W2 buf0

    // -------- GEMM2: h[64x128] @ W2 --------
    for (int c = 0; c < 4; c++) {
        int buf = c & 1;
        if (c < 3) fetchB(W2, c + 1);
        mmastep(sH + c * 32, LDH, sB + buf * B_CH);
        if (c < 3) {
            storeB(buf ^ 1);
            __syncthreads();
        }
    }

    // -------- epilogue 2: out = D2 + b2 --------
    #pragma unroll
    for (int mt = 0; mt < 2; mt++) {
        int row = m0 + 16 * mt + g;
        float* o0 = out + (size_t)(rowBase + row) * 128;
        float* o1 = out + (size_t)(rowBase + row + 8) * 128;
        #pragma unroll
        for (int nt = 0; nt < 4; nt++) {
            int col = n0 + 8 * nt + 2 * tig;
            *(float2*)(o0 + col) = make_float2(acc[mt][nt][0] + b2s[col],
                                               acc[mt][nt][1] + b2s[col + 1]);
            *(float2*)(o1 + col) = make_float2(acc[mt][nt][2] + b2s[col],
                                               acc[mt][nt][3] + b2s[col + 1]);
        }
    }
}

// ---------------- scatter cell outputs to node sums + counts ----------------
__global__ void scatter_cell_kernel(const float* __restrict__ cell_out,
                                    const int*   __restrict__ face,
                                    float* __restrict__ node_out) {
    int w    = (blockIdx.x * blockDim.x + threadIdx.x) >> 5;
    int lane = threadIdx.x & 31;
    if (w >= THREEC) return;
    int node = face[w];
    int c = w;
    if (c >= NCELLS) c -= NCELLS;
    if (c >= NCELLS) c -= NCELLS;

    float4 v = __ldg(((const float4*)cell_out) + (size_t)c * 32 + lane);
    float* dst = node_out + (size_t)node * DIM + lane * 4;
    asm volatile("red.global.add.v4.f32 [%0], {%1,%2,%3,%4};"
                 :: "l"(dst), "f"(v.x), "f"(v.y), "f"(v.z), "f"(v.w)
                 : "memory");
    if (lane == 0) atomicAdd(&g_counts[node], 1.f);
}

__global__ void finalize_kernel(float* __restrict__ node_out) {
    int i = blockIdx.x * 256 + threadIdx.x;
    if (i >= NNODES * DIM / 4) return;
    float inv = 1.f / fmaxf(g_counts[i >> 5], 1.f);
    float4 v = ((float4*)node_out)[i];
    v.x *= inv; v.y *= inv; v.z *= inv; v.w *= inv;
    ((float4*)node_out)[i] = v;
}

// ---------------- launch ----------------
extern "C" void kernel_launch(void* const* d_in, const int* in_sizes, int n_in,
                              void* d_out, int out_size) {
    const float* cell_attr  = (const float*)d_in[0];
    const float* edge_attr  = (const float*)d_in[1];
    const float* node_emb   = (const float*)d_in[2];
    const int*   edge_index = (const int*)d_in[3];
    const int*   face       = (const int*)d_in[4];
    const float* W1 = (const float*)d_in[5];
    const float* b1 = (const float*)d_in[6];
    const float* W2 = (const float*)d_in[7];
    const float* b2 = (const float*)d_in[8];

    float* out      = (float*)d_out;
    float* cell_out = out;
    float* node_out = out + (size_t)NCELLS * DIM;

    cudaFuncSetAttribute(mlp_mma_kernel,
                         cudaFuncAttributeMaxDynamicSharedMemorySize, MLP_SMEM);

    zero_kernel<<<50000, 256>>>(node_out);
    attn_kernel<<<37500, 256>>>(edge_attr, node_emb, edge_index);
    mlp_mma_kernel<<<3125, 256, MLP_SMEM>>>(cell_attr, face, W1, b1, W2, b2, cell_out);
    scatter_cell_kernel<<<75000, 256>>>(cell_out, face, node_out);
    finalize_kernel<<<12500, 256>>>(node_out);
}